// round 5
// baseline (speedup 1.0000x reference)
#include <cuda_runtime.h>
#include <math.h>

#define Bq   4
#define Cc   96
#define HWp  16384
#define NTOT (Bq*Cc*HWp)          // 6291456
#define CROW2 40                   // conv smem row stride (ull)

typedef unsigned long long ull;

__device__ __forceinline__ ull pk2(float lo, float hi) {
    ull r; asm("mov.b64 %0,{%1,%2};" : "=l"(r) : "f"(lo), "f"(hi)); return r;
}
__device__ __forceinline__ void upk(ull v, float& lo, float& hi) {
    asm("mov.b64 {%0,%1},%2;" : "=f"(lo), "=f"(hi) : "l"(v));
}
__device__ __forceinline__ void ffma2(ull& d, ull a, ull b) {
    asm("fma.rn.f32x2 %0,%1,%2,%0;" : "+l"(d) : "l"(a), "l"(b));
}
__device__ __forceinline__ float gelu_ex(float x) {
    return 0.5f * x * (1.f + erff(x * 0.70710678118654752f));
}
__device__ __forceinline__ unsigned smem_u32(const void* p) {
    return (unsigned)__cvta_generic_to_shared(p);
}
__device__ __forceinline__ void cp16(unsigned dst, const void* src, int n) {
    asm volatile("cp.async.cg.shared.global [%0],[%1],16,%2;" :: "r"(dst), "l"(src), "r"(n));
}
#define CP_COMMIT() asm volatile("cp.async.commit_group;")
#define CP_WAIT0()  asm volatile("cp.async.wait_group 0;")

// ---------------- device scratch ----------------
__device__ ull   g_xi[NTOT];        // interleaved (x1,x2) pairs, CHW
__device__ ull   g_weffP[96*96*9];  // (w1eff,w2eff) pairs
__device__ float g_DT[128*128];
__device__ ull   g_DpD[128*128];    // dup pairs: [(row>>1)*128+col]*2 + (row&1)
__device__ ull   g_WcombP[96*96];   // dup
__device__ float g_bcomb[96];
__device__ ull   g_W1P[96*384];     // dup, [k*384+j]
__device__ ull   g_W2P[384*96];     // dup, [j*96+i]
__device__ float g_tokA[NTOT];
__device__ float g_tokB[NTOT];
__device__ float g_cross[NTOT];
__device__ float g_dct[NTOT];
__device__ float g_energy[Bq*HWp];
__device__ float g_scale[Bq];

// ---------------- interleave x1,x2 into pair array ----------------
__global__ void k_ilv(const float* __restrict__ x1, const float* __restrict__ x2) {
    int g = blockIdx.x * blockDim.x + threadIdx.x;   // NTOT/4
    float4 a = ((const float4*)x1)[g];
    float4 b = ((const float4*)x2)[g];
    ((float4*)g_xi)[2 * g]     = make_float4(a.x, b.x, a.y, b.y);
    ((float4*)g_xi)[2 * g + 1] = make_float4(a.z, b.z, a.w, b.w);
}

// ---------------- LDC effective weights, packed (w1,w2) ----------------
__global__ void k_weffP(const float* __restrict__ w1, const float* __restrict__ lm1,
                        const float* __restrict__ th1,
                        const float* __restrict__ w2, const float* __restrict__ lm2,
                        const float* __restrict__ th2) {
    int t = blockIdx.x * 256 + threadIdx.x;
    if (t >= 96 * 96) return;
    const float* ws1 = w1 + t * 9;
    const float* ws2 = w2 + t * 9;
    float s1 = 0.f, s2 = 0.f;
#pragma unroll
    for (int k = 0; k < 9; k++) { s1 += ws1[k]; s2 += ws2[k]; }
    float sc1 = 1.f - th1[0] * lm1[t] * s1;
    float sc2 = 1.f - th2[0] * lm2[t] * s2;
    ull* o = g_weffP + t * 9;
#pragma unroll
    for (int k = 0; k < 9; k++) o[k] = pk2(ws1[k], ws2[k]);
    o[4] = pk2(ws1[4] * sc1, ws2[4] * sc2);
}

// ---------------- init: DCT-II matrices ----------------
__global__ void k_init_dct() {
    int t = blockIdx.x * blockDim.x + threadIdx.x;   // 16384
    int k = t >> 7, i = t & 127;
    float arg = (float)((2 * i + 1) * k) * (1.0f / 256.0f);
    float v = cospif(arg) * 0.125f;
    if (k == 0) v *= 0.70710678118654752440f;
    g_DT[i * 128 + k] = v;
    g_DpD[((k >> 1) * 128 + i) * 2 + (k & 1)] = pk2(v, v);
}

// ---------------- prep: Wcomb dup, bcomb, MLP dup transposes ----------------
__global__ void k_prep2(const float* __restrict__ qkv_w, const float* __restrict__ qkv_b,
                        const float* __restrict__ proj_w, const float* __restrict__ proj_b,
                        const float* __restrict__ w1, const float* __restrict__ w2) {
    int blk = blockIdx.x, tid = threadIdx.x;
    if (blk < 96) {
        if (tid < 96) {
            float s = 0.f;
            for (int m = 0; m < 96; m++)
                s += proj_w[blk * 96 + m] * qkv_w[(192 + m) * 96 + tid];
            g_WcombP[tid * 96 + blk] = pk2(s, s);
        }
    } else if (blk == 96) {
        if (tid < 96) {
            float s = proj_b[tid];
            for (int m = 0; m < 96; m++)
                s += proj_w[tid * 96 + m] * qkv_b[192 + m];
            g_bcomb[tid] = s;
        }
    } else {
        int t = (blk - 97) * 256 + tid;
        if (t < 96 * 384) {
            { int k = t / 384, j = t % 384; float v = w1[j * 96 + k]; g_W1P[t] = pk2(v, v); }
            { int k = t / 96,  i = t % 96;  float v = w2[i * 384 + k]; g_W2P[t] = pk2(v, v); }
        }
    }
}

// ---------------- fused double conv + residual, (x1,x2)-pair lanes ----------------
__global__ void __launch_bounds__(256, 2)
k_conv() {
    __shared__ __align__(16) ull sIn[2][34 * CROW2];
    __shared__ __align__(16) ull wS[2][80];           // [buf][co*10+k]
    int tid = threadIdx.x;
    int b   = blockIdx.z;
    int cob = blockIdx.y * 8;
    int bt  = blockIdx.x;
    int y0  = (bt >> 2) * 32, x0 = (bt & 3) * 32;
    const ull* Xb = g_xi + (size_t)b * 96 * HWp;
    int ty = tid >> 4, tx = tid & 15;
    int py = ty * 2, px = tx * 2;

    // channel-invariant load slots: 34 rows x 18 chunks (16B = 2 ull cols)
    const char* gsrc[3]; unsigned sdst[3]; int csz[3];
    int nslot = 0;
#pragma unroll
    for (int n = 0; n < 3; n++) {
        int s = tid + n * 256;
        if (s < 612) {
            int r = s / 18, ch = s % 18;
            int gy = y0 - 1 + r;
            int gx = x0 - 2 + 2 * ch;
            bool ok = (gy >= 0) && (gy < 128) && (gx >= 0) && (gx < 128);
            int goff = ok ? (gy * 128 + gx) : 0;
            gsrc[n] = (const char*)(Xb + goff);
            sdst[n] = smem_u32(&sIn[0][r * CROW2 + 2 * ch]);
            csz[n]  = ok ? 16 : 0;
            nslot = n + 1;
        }
    }

    auto issue = [&](int ci, int buf) {
        unsigned bofs = buf ? (unsigned)sizeof(sIn[0]) : 0u;
        size_t gofs = (size_t)ci * (HWp * 8);
#pragma unroll
        for (int n = 0; n < 3; n++)
            if (n < nslot) cp16(sdst[n] + bofs, gsrc[n] + gofs, csz[n]);
        CP_COMMIT();
    };
    auto wload = [&](int ci, int buf) {
        if (tid < 72) {
            int co = tid / 9, k = tid % 9;
            wS[buf][co * 10 + k] = g_weffP[((cob + co) * 96 + ci) * 9 + k];
        }
    };

    issue(0, 0);
    wload(0, 0);

    ull acc[8][4];
#pragma unroll
    for (int i = 0; i < 8; i++)
#pragma unroll
        for (int j = 0; j < 4; j++) acc[i][j] = 0ULL;
    const ull TWO = pk2(2.f, 2.f);

    for (int ci = 0; ci < 96; ci++) {
        int cur = ci & 1;
        CP_WAIT0();
        __syncthreads();
        if (ci < 95) { issue(ci + 1, cur ^ 1); wload(ci + 1, cur ^ 1); }

        ull rp[4][4];
#pragma unroll
        for (int i = 0; i < 4; i++)
#pragma unroll
            for (int j = 0; j < 4; j++)
                rp[i][j] = sIn[cur][(py + i) * CROW2 + px + 1 + j];

#pragma unroll
        for (int co = 0; co < 8; co++) {
#pragma unroll
            for (int ky = 0; ky < 3; ky++)
#pragma unroll
                for (int kx = 0; kx < 3; kx++) {
                    ull w = wS[cur][co * 10 + ky * 3 + kx];
                    ffma2(acc[co][0], rp[ky][kx], w);
                    ffma2(acc[co][1], rp[ky][kx + 1], w);
                    ffma2(acc[co][2], rp[ky + 1][kx], w);
                    ffma2(acc[co][3], rp[ky + 1][kx + 1], w);
                }
        }
        int cc = ci - cob;
        if (cc >= 0 && cc < 8) {
            ffma2(acc[cc][0], rp[1][1], TWO);
            ffma2(acc[cc][1], rp[1][2], TWO);
            ffma2(acc[cc][2], rp[2][1], TWO);
            ffma2(acc[cc][3], rp[2][2], TWO);
        }
    }

    // store token-major: result = lo + hi
#pragma unroll
    for (int r = 0; r < 2; r++)
#pragma unroll
        for (int c = 0; c < 2; c++) {
            float v[8];
#pragma unroll
            for (int co = 0; co < 8; co++) {
                float lo, hi; upk(acc[co][r * 2 + c], lo, hi);
                v[co] = lo + hi;
            }
            size_t tok = (size_t)b * HWp + (size_t)(y0 + py + r) * 128 + (x0 + px + c);
            float* d = g_tokA + tok * 96 + cob;
            ((float4*)d)[0] = make_float4(v[0], v[1], v[2], v[3]);
            ((float4*)d)[1] = make_float4(v[4], v[5], v[6], v[7]);
        }
}

// ---------------- swin attention (folded), [ch][tok] smem, dup weights ----------------
__global__ void __launch_bounds__(256)
k_attn(const float* __restrict__ g1, const float* __restrict__ b1) {
    __shared__ float tns2[8][960];    // [warp][ch*10 + tok]
    int warp = threadIdx.x >> 5, lane = threadIdx.x & 31;
    int tokbase = blockIdx.x * 64 + warp * 8;
    float tv[8][3];
#pragma unroll
    for (int t = 0; t < 8; t++) {
        const float* tp = g_tokA + (size_t)(tokbase + t) * 96;
        float a = tp[lane], bb = tp[lane + 32], cc = tp[lane + 64];
        tv[t][0] = a; tv[t][1] = bb; tv[t][2] = cc;
        float s = a + bb + cc;
#pragma unroll
        for (int o = 16; o; o >>= 1) s += __shfl_xor_sync(0xffffffff, s, o);
        float m = s * (1.f / 96.f);
        float d0 = a - m, d1 = bb - m, d2 = cc - m;
        float q = d0 * d0 + d1 * d1 + d2 * d2;
#pragma unroll
        for (int o = 16; o; o >>= 1) q += __shfl_xor_sync(0xffffffff, q, o);
        float rstd = rsqrtf(q * (1.f / 96.f) + 1e-5f);
        tns2[warp][lane * 10 + t]        = d0 * rstd * g1[lane]      + b1[lane];
        tns2[warp][(lane + 32) * 10 + t] = d1 * rstd * g1[lane + 32] + b1[lane + 32];
        tns2[warp][(lane + 64) * 10 + t] = d2 * rstd * g1[lane + 64] + b1[lane + 64];
    }
    __syncwarp();
    ull acc[4][3];
#pragma unroll
    for (int p = 0; p < 4; p++) { acc[p][0] = 0; acc[p][1] = 0; acc[p][2] = 0; }
    for (int k = 0; k < 96; k++) {
        ull W0 = g_WcombP[k * 96 + lane];
        ull W1 = g_WcombP[k * 96 + lane + 32];
        ull W2 = g_WcombP[k * 96 + lane + 64];
#pragma unroll
        for (int p = 0; p < 4; p++) {
            ull sp = *(const ull*)&tns2[warp][k * 10 + 2 * p];
            ffma2(acc[p][0], sp, W0);
            ffma2(acc[p][1], sp, W1);
            ffma2(acc[p][2], sp, W2);
        }
    }
#pragma unroll
    for (int p = 0; p < 4; p++) {
#pragma unroll
        for (int c = 0; c < 3; c++) {
            float o0, o1; upk(acc[p][c], o0, o1);
            int ch = lane + 32 * c;
            g_tokB[(size_t)(tokbase + 2 * p) * 96 + ch]     = tv[2 * p][c]     + o0 + g_bcomb[ch];
            g_tokB[(size_t)(tokbase + 2 * p + 1) * 96 + ch] = tv[2 * p + 1][c] + o1 + g_bcomb[ch];
        }
    }
}

// ---------------- swin MLP, [ch][tok] smem, dup weights, j-halved ----------------
__global__ void __launch_bounds__(256)
k_mlp(const float* __restrict__ g2, const float* __restrict__ b2,
      const float* __restrict__ mb1, const float* __restrict__ mb2) {
    extern __shared__ float sm[];
    float* tnP = sm;            // [8][960]
    float* hsP = sm + 7680;     // [8][1920]
    int warp = threadIdx.x >> 5, lane = threadIdx.x & 31;
    int tokbase = blockIdx.x * 64 + warp * 8;
    float* tnw = tnP + warp * 960;
    float* hsw = hsP + warp * 1920;
    float tv[8][3];
#pragma unroll
    for (int t = 0; t < 8; t++) {
        const float* tp = g_tokB + (size_t)(tokbase + t) * 96;
        float a = tp[lane], bb = tp[lane + 32], cc = tp[lane + 64];
        tv[t][0] = a; tv[t][1] = bb; tv[t][2] = cc;
        float s = a + bb + cc;
#pragma unroll
        for (int o = 16; o; o >>= 1) s += __shfl_xor_sync(0xffffffff, s, o);
        float m = s * (1.f / 96.f);
        float d0 = a - m, d1 = bb - m, d2 = cc - m;
        float q = d0 * d0 + d1 * d1 + d2 * d2;
#pragma unroll
        for (int o = 16; o; o >>= 1) q += __shfl_xor_sync(0xffffffff, q, o);
        float rstd = rsqrtf(q * (1.f / 96.f) + 1e-5f);
        tnw[lane * 10 + t]        = d0 * rstd * g2[lane]      + b2[lane];
        tnw[(lane + 32) * 10 + t] = d1 * rstd * g2[lane + 32] + b2[lane + 32];
        tnw[(lane + 64) * 10 + t] = d2 * rstd * g2[lane + 64] + b2[lane + 64];
    }
    __syncwarp();
    ull oacc[4][3];
#pragma unroll
    for (int p = 0; p < 4; p++) { oacc[p][0] = 0; oacc[p][1] = 0; oacc[p][2] = 0; }

    for (int half = 0; half < 2; half++) {
        ull h[4][6];
#pragma unroll
        for (int p = 0; p < 4; p++)
#pragma unroll
            for (int r = 0; r < 6; r++) h[p][r] = 0;
        const ull* w1p = g_W1P + half * 192 + lane;
        for (int k = 0; k < 96; k++) {
            ull W[6];
#pragma unroll
            for (int r = 0; r < 6; r++) W[r] = w1p[k * 384 + 32 * r];
#pragma unroll
            for (int p = 0; p < 4; p++) {
                ull sp = *(const ull*)&tnw[k * 10 + 2 * p];
#pragma unroll
                for (int r = 0; r < 6; r++) ffma2(h[p][r], sp, W[r]);
            }
        }
#pragma unroll
        for (int p = 0; p < 4; p++)
#pragma unroll
            for (int r = 0; r < 6; r++) {
                int j = lane + 32 * r;
                float bias = mb1[half * 192 + j];
                float x0, x1; upk(h[p][r], x0, x1);
                hsw[j * 10 + 2 * p]     = gelu_ex(x0 + bias);
                hsw[j * 10 + 2 * p + 1] = gelu_ex(x1 + bias);
            }
        __syncwarp();
        const ull* w2p = g_W2P + (size_t)(half * 192) * 96;
        for (int j = 0; j < 192; j++) {
            ull U0 = w2p[j * 96 + lane];
            ull U1 = w2p[j * 96 + lane + 32];
            ull U2 = w2p[j * 96 + lane + 64];
#pragma unroll
            for (int p = 0; p < 4; p++) {
                ull hp = *(const ull*)&hsw[j * 10 + 2 * p];
                ffma2(oacc[p][0], hp, U0);
                ffma2(oacc[p][1], hp, U1);
                ffma2(oacc[p][2], hp, U2);
            }
        }
        __syncwarp();
    }
#pragma unroll
    for (int p = 0; p < 4; p++) {
#pragma unroll
        for (int c = 0; c < 3; c++) {
            float o0, o1; upk(oacc[p][c], o0, o1);
            int ch = lane + 32 * c;
            g_tokA[(size_t)(tokbase + 2 * p) * 96 + ch]     = tv[2 * p][c]     + o0 + mb2[ch];
            g_tokA[(size_t)(tokbase + 2 * p + 1) * 96 + ch] = tv[2 * p + 1][c] + o1 + mb2[ch];
        }
    }
}

// ---------------- transpose token-major -> CHW ----------------
__global__ void k_t2() {
    __shared__ float tile[32][33];
    int b = blockIdx.z, c0 = blockIdx.y * 32, p0 = blockIdx.x * 32;
    int tx = threadIdx.x, ty0 = threadIdx.y;
    for (int yy = ty0; yy < 32; yy += 8)
        tile[yy][tx] = g_tokA[(size_t)(b * HWp + p0 + yy) * 96 + c0 + tx];
    __syncthreads();
    for (int yy = ty0; yy < 32; yy += 8)
        g_cross[(size_t)(b * 96 + c0 + yy) * HWp + p0 + tx] = tile[tx][yy];
}

// ---------------- 2D DCT per (b,c), dup-pair weights, dup Ys ----------------
__global__ void __launch_bounds__(256) k_dct() {
    extern __shared__ float sm[];
    float* Xs = sm;                       // 16384 floats (64KB)
    ull*   YsD = (ull*)(sm + 16384);      // 16384 ull (128KB), dup values
    int bc = blockIdx.x;
    int tid = threadIdx.x;
    const float4* src = (const float4*)(g_cross + (size_t)bc * HWp);
    float4* Xs4 = (float4*)Xs;
    for (int l = tid; l < 4096; l += 256) Xs4[l] = src[l];
    __syncthreads();

    int jq = tid & 31;
    int ig = tid >> 5;
    int j0 = 2 * jq, j2 = 64 + 2 * jq;

    for (int ii = 0; ii < 8; ii++) {
        int ip = ig + ii * 8;
        ull a00 = 0, a01 = 0, a10 = 0, a11 = 0;
        const ull* dp = g_DpD + ip * 256;
#pragma unroll 4
        for (int k = 0; k < 128; k++) {
            ull D0 = dp[2 * k], D1 = dp[2 * k + 1];
            ull xA = *(const ull*)&Xs[k * 128 + j0];
            ull xB = *(const ull*)&Xs[k * 128 + j2];
            ffma2(a00, xA, D0); ffma2(a01, xB, D0);
            ffma2(a10, xA, D1); ffma2(a11, xB, D1);
        }
        float l, h;
        upk(a00, l, h); YsD[(2*ip)*128 + j0] = pk2(l,l);   YsD[(2*ip)*128 + j0+1] = pk2(h,h);
        upk(a01, l, h); YsD[(2*ip)*128 + j2] = pk2(l,l);   YsD[(2*ip)*128 + j2+1] = pk2(h,h);
        upk(a10, l, h); YsD[(2*ip+1)*128 + j0] = pk2(l,l); YsD[(2*ip+1)*128 + j0+1] = pk2(h,h);
        upk(a11, l, h); YsD[(2*ip+1)*128 + j2] = pk2(l,l); YsD[(2*ip+1)*128 + j2+1] = pk2(h,h);
    }
    __syncthreads();

    ull acc[8][4];
#pragma unroll
    for (int ii = 0; ii < 8; ii++)
#pragma unroll
        for (int q = 0; q < 4; q++) acc[ii][q] = 0;
    for (int k = 0; k < 128; k++) {
        ull dtA = *(const ull*)&g_DT[k * 128 + j0];
        ull dtB = *(const ull*)&g_DT[k * 128 + j2];
#pragma unroll
        for (int ii = 0; ii < 8; ii++) {
            int ip = ig + ii * 8;
            ull Y0 = YsD[(2*ip)*128 + k];
            ull Y1 = YsD[(2*ip+1)*128 + k];
            ffma2(acc[ii][0], dtA, Y0); ffma2(acc[ii][1], dtB, Y0);
            ffma2(acc[ii][2], dtA, Y1); ffma2(acc[ii][3], dtB, Y1);
        }
    }
    float* dst = g_dct + (size_t)bc * HWp;
#pragma unroll
    for (int ii = 0; ii < 8; ii++) {
        int ip = ig + ii * 8;
        *(ull*)&dst[(2*ip)*128 + j0]   = acc[ii][0];
        *(ull*)&dst[(2*ip)*128 + j2]   = acc[ii][1];
        *(ull*)&dst[(2*ip+1)*128 + j0] = acc[ii][2];
        *(ull*)&dst[(2*ip+1)*128 + j2] = acc[ii][3];
    }
}

// ---------------- channel-mean |dct| (float4) ----------------
__global__ void k_energy() {
    int g = blockIdx.x * blockDim.x + threadIdx.x;   // 16384
    int b = g >> 12, p4 = g & 4095;
    const float4* base = (const float4*)(g_dct + (size_t)b * 96 * HWp) + p4;
    float4 s = make_float4(0.f, 0.f, 0.f, 0.f);
    for (int c = 0; c < 96; c++) {
        float4 v = base[(size_t)c * 4096];
        s.x += fabsf(v.x); s.y += fabsf(v.y); s.z += fabsf(v.z); s.w += fabsf(v.w);
    }
    float inv = 1.f / 96.f;
    s.x *= inv; s.y *= inv; s.z *= inv; s.w *= inv;
    ((float4*)(g_energy + b * HWp))[p4] = s;
}

// ---------------- top-96 via histogram threshold + rank sort ----------------
__global__ void __launch_bounds__(256)
k_topk(const float* __restrict__ fw1, const float* __restrict__ fb1,
       const float* __restrict__ fw2, const float* __restrict__ fb2) {
    extern __shared__ float e[];                 // 16384 floats
    int* hist = (int*)(e + 16384);               // 4096 ints (reused as cand)
    __shared__ int csum[256];
    __shared__ int s_T, s_cnt;
    __shared__ float tk[96];
    __shared__ float hh[24];
    int b = blockIdx.x, tid = threadIdx.x;

    const float4* src = (const float4*)(g_energy + b * HWp);
    float4* e4 = (float4*)e;
    for (int l = tid; l < 4096; l += 256) e4[l] = src[l];
    for (int l = tid; l < 4096; l += 256) hist[l] = 0;
    __syncthreads();
    for (int l = tid; l < 16384; l += 256) {
        int key = (int)(__float_as_uint(e[l]) >> 19);
        atomicAdd(&hist[key], 1);
    }
    __syncthreads();
    {
        int s = 0;
#pragma unroll
        for (int k = 0; k < 16; k++) s += hist[tid * 16 + k];
        csum[tid] = s;
    }
    __syncthreads();
    if (tid == 0) {
        int run = 0, cstar = 0;
        for (int c = 255; c >= 0; c--) {
            if (run + csum[c] >= 96) { cstar = c; break; }
            run += csum[c];
        }
        int T = cstar * 16;
        for (int k = 15; k >= 0; k--) {
            int bin = cstar * 16 + k;
            if (run + hist[bin] >= 96) { T = bin; break; }
            run += hist[bin];
        }
        s_T = T; s_cnt = 0;
    }
    __syncthreads();
    int T = s_T;
    float* cand = (float*)hist;
    __syncthreads();
    for (int l = tid; l < 16384; l += 256) {
        float v = e[l];
        if ((int)(__float_as_uint(v) >> 19) >= T) {
            int pos = atomicAdd(&s_cnt, 1);
            if (pos < 4096) cand[pos] = v;
        }
    }
    __syncthreads();
    int M = s_cnt; if (M > 4096) M = 4096;
    for (int i = tid; i < M; i += 256) {
        float v = cand[i];
        int r = 0;
        for (int j = 0; j < M; j++) {
            float u = cand[j];
            r += (u > v) || (u == v && j < i);
        }
        if (r < 96) tk[r] = v;
    }
    __syncthreads();
    if (tid < 24) {
        float s = fb1[tid];
        for (int k = 0; k < 96; k++) s += tk[k] * fw1[tid * 96 + k];
        hh[tid] = fmaxf(s, 0.f);
    }
    __syncthreads();
    if (tid == 0) {
        float a = fb2[0];
        for (int j = 0; j < 24; j++) a += hh[j] * fw2[j];
        g_scale[b] = 1.f + 1.f / (1.f + expf(-a));
    }
}

// ---------------- epilogue (float4) ----------------
__global__ void k_final(const float* __restrict__ x1, const float* __restrict__ x2,
                        float* __restrict__ out) {
    int i = blockIdx.x * blockDim.x + threadIdx.x;   // NTOT/4
    float s = g_scale[i / (96 * HWp / 4)];
    float4 c = ((const float4*)g_cross)[i];
    float4 a = ((const float4*)x1)[i];
    float4 b = ((const float4*)x2)[i];
    float4 o1, o2;
    o1.x = a.x + s * c.x; o1.y = a.y + s * c.y; o1.z = a.z + s * c.z; o1.w = a.w + s * c.w;
    o2.x = b.x + s * c.x; o2.y = b.y + s * c.y; o2.z = b.z + s * c.z; o2.w = b.w + s * c.w;
    ((float4*)out)[i]            = o1;
    ((float4*)out)[NTOT / 4 + i] = o2;
}

extern "C" void kernel_launch(void* const* d_in, const int* in_sizes, int n_in,
                              void* d_out, int out_size) {
    const float* x1     = (const float*)d_in[0];
    const float* x2     = (const float*)d_in[1];
    const float* w_tx1  = (const float*)d_in[2];
    const float* lm1    = (const float*)d_in[3];
    const float* theta1 = (const float*)d_in[4];
    const float* w_tx2  = (const float*)d_in[5];
    const float* lm2    = (const float*)d_in[6];
    const float* theta2 = (const float*)d_in[7];
    const float* ln1_g  = (const float*)d_in[8];
    const float* ln1_b  = (const float*)d_in[9];
    const float* qkv_w  = (const float*)d_in[10];
    const float* qkv_b  = (const float*)d_in[11];
    const float* proj_w = (const float*)d_in[12];
    const float* proj_b = (const float*)d_in[13];
    const float* ln2_g  = (const float*)d_in[14];
    const float* ln2_b  = (const float*)d_in[15];
    const float* mlp_w1 = (const float*)d_in[16];
    const float* mlp_b1 = (const float*)d_in[17];
    const float* mlp_w2 = (const float*)d_in[18];
    const float* mlp_b2 = (const float*)d_in[19];
    const float* fc_w1  = (const float*)d_in[20];
    const float* fc_b1  = (const float*)d_in[21];
    const float* fc_w2  = (const float*)d_in[22];
    const float* fc_b2  = (const float*)d_in[23];
    float* out = (float*)d_out;

    cudaFuncSetAttribute(k_dct,  cudaFuncAttributeMaxDynamicSharedMemorySize, 196608);
    cudaFuncSetAttribute(k_topk, cudaFuncAttributeMaxDynamicSharedMemorySize, 81920);
    cudaFuncSetAttribute(k_mlp,  cudaFuncAttributeMaxDynamicSharedMemorySize, 92160);

    // slot 4 (ncu capture) = k_conv
    k_ilv<<<NTOT / 4 / 256, 256>>>(x1, x2);
    k_weffP<<<36, 256>>>(w_tx1, lm1, theta1, w_tx2, lm2, theta2);
    k_prep2<<<241, 256>>>(qkv_w, qkv_b, proj_w, proj_b, mlp_w1, mlp_w2);
    k_conv<<<dim3(16, 12, 4), 256>>>();
    k_attn<<<1024, 256>>>(ln1_g, ln1_b);
    k_mlp<<<1024, 256, 92160>>>(ln2_g, ln2_b, mlp_b1, mlp_b2);
    k_init_dct<<<64, 256>>>();
    k_t2<<<dim3(512, 3, 4), dim3(32, 8)>>>();
    k_dct<<<384, 256, 196608>>>();
    k_energy<<<64, 256>>>();
    k_topk<<<4, 256, 81920>>>(fc_w1, fc_b1, fc_w2, fc_b2);
    k_final<<<NTOT / 4 / 256, 256>>>(x1, x2, out);
}

// round 6
// speedup vs baseline: 1.0878x; 1.0878x over previous
#include <cuda_runtime.h>
#include <math.h>

#define Bq   4
#define Cc   96
#define HWp  16384
#define NTOT (Bq*Cc*HWp)          // 6291456
#define CROW2 40                   // conv smem row stride (ull)

typedef unsigned long long ull;

__device__ __forceinline__ ull pk2(float lo, float hi) {
    ull r; asm("mov.b64 %0,{%1,%2};" : "=l"(r) : "f"(lo), "f"(hi)); return r;
}
__device__ __forceinline__ void upk(ull v, float& lo, float& hi) {
    asm("mov.b64 {%0,%1},%2;" : "=f"(lo), "=f"(hi) : "l"(v));
}
__device__ __forceinline__ void ffma2(ull& d, ull a, ull b) {
    asm("fma.rn.f32x2 %0,%1,%2,%0;" : "+l"(d) : "l"(a), "l"(b));
}
__device__ __forceinline__ float gelu_ex(float x) {
    return 0.5f * x * (1.f + erff(x * 0.70710678118654752f));
}
__device__ __forceinline__ unsigned smem_u32(const void* p) {
    return (unsigned)__cvta_generic_to_shared(p);
}
__device__ __forceinline__ void cp16(unsigned dst, const void* src, int n) {
    asm volatile("cp.async.cg.shared.global [%0],[%1],16,%2;" :: "r"(dst), "l"(src), "r"(n));
}
#define CP_COMMIT() asm volatile("cp.async.commit_group;")
#define CP_WAIT0()  asm volatile("cp.async.wait_group 0;")

// ---------------- device scratch ----------------
__device__ ull   g_xi[NTOT];        // interleaved (x1,x2) pairs, CHW
__device__ ull   g_weffP[96*96*9];  // (w1eff,w2eff) pairs
__device__ float g_DT[128*128];
__device__ ull   g_DpD[128*128];    // dup pairs for DCT stage-1
__device__ ull   g_WcombP[96*96];   // dup
__device__ float g_bcomb[96];
__device__ ull   g_W1P[96*384];     // dup, [k*384+j]
__device__ ull   g_W2P[384*96];     // dup, [j*96+i]
__device__ float g_tokA[NTOT];
__device__ float g_tokB[NTOT];
__device__ float g_cross[NTOT];
__device__ float g_dct[NTOT];
__device__ float g_energy[Bq*HWp];
__device__ float g_scale[Bq];

// ---------------- interleave x1,x2 into pair array ----------------
__global__ void k_ilv(const float* __restrict__ x1, const float* __restrict__ x2) {
    int g = blockIdx.x * blockDim.x + threadIdx.x;   // NTOT/4
    float4 a = ((const float4*)x1)[g];
    float4 b = ((const float4*)x2)[g];
    ((float4*)g_xi)[2 * g]     = make_float4(a.x, b.x, a.y, b.y);
    ((float4*)g_xi)[2 * g + 1] = make_float4(a.z, b.z, a.w, b.w);
}

// ---------------- LDC effective weights, packed (w1,w2) ----------------
__global__ void k_weffP(const float* __restrict__ w1, const float* __restrict__ lm1,
                        const float* __restrict__ th1,
                        const float* __restrict__ w2, const float* __restrict__ lm2,
                        const float* __restrict__ th2) {
    int t = blockIdx.x * 256 + threadIdx.x;
    if (t >= 96 * 96) return;
    const float* ws1 = w1 + t * 9;
    const float* ws2 = w2 + t * 9;
    float s1 = 0.f, s2 = 0.f;
#pragma unroll
    for (int k = 0; k < 9; k++) { s1 += ws1[k]; s2 += ws2[k]; }
    float sc1 = 1.f - th1[0] * lm1[t] * s1;
    float sc2 = 1.f - th2[0] * lm2[t] * s2;
    ull* o = g_weffP + t * 9;
#pragma unroll
    for (int k = 0; k < 9; k++) o[k] = pk2(ws1[k], ws2[k]);
    o[4] = pk2(ws1[4] * sc1, ws2[4] * sc2);
}

// ---------------- init: DCT-II matrices ----------------
__global__ void k_init_dct() {
    int t = blockIdx.x * blockDim.x + threadIdx.x;   // 16384
    int k = t >> 7, i = t & 127;
    float arg = (float)((2 * i + 1) * k) * (1.0f / 256.0f);
    float v = cospif(arg) * 0.125f;
    if (k == 0) v *= 0.70710678118654752440f;
    g_DT[i * 128 + k] = v;
    g_DpD[((k >> 1) * 128 + i) * 2 + (k & 1)] = pk2(v, v);
}

// ---------------- prep: Wcomb dup, bcomb, MLP dup transposes ----------------
__global__ void k_prep2(const float* __restrict__ qkv_w, const float* __restrict__ qkv_b,
                        const float* __restrict__ proj_w, const float* __restrict__ proj_b,
                        const float* __restrict__ w1, const float* __restrict__ w2) {
    int blk = blockIdx.x, tid = threadIdx.x;
    if (blk < 96) {
        if (tid < 96) {
            float s = 0.f;
            for (int m = 0; m < 96; m++)
                s += proj_w[blk * 96 + m] * qkv_w[(192 + m) * 96 + tid];
            g_WcombP[tid * 96 + blk] = pk2(s, s);
        }
    } else if (blk == 96) {
        if (tid < 96) {
            float s = proj_b[tid];
            for (int m = 0; m < 96; m++)
                s += proj_w[tid * 96 + m] * qkv_b[192 + m];
            g_bcomb[tid] = s;
        }
    } else {
        int t = (blk - 97) * 256 + tid;
        if (t < 96 * 384) {
            { int k = t / 384, j = t % 384; float v = w1[j * 96 + k]; g_W1P[t] = pk2(v, v); }
            { int k = t / 96,  i = t % 96;  float v = w2[i * 384 + k]; g_W2P[t] = pk2(v, v); }
        }
    }
}

// ---------------- fused double conv + residual, 2-channel pipeline stages ----------------
// dynamic smem: sIn[2 stages][2 ch][34*CROW2] ull = 87040 B
__global__ void __launch_bounds__(256, 2)
k_conv() {
    extern __shared__ __align__(16) ull sIn[];      // [st][c2][1360]
    __shared__ __align__(16) ull wS[2][2][80];      // [st][c2][co*10+k]
    int tid = threadIdx.x;
    int b   = blockIdx.z;
    int cob = blockIdx.y * 8;
    int bt  = blockIdx.x;
    int y0  = (bt >> 2) * 32, x0 = (bt & 3) * 32;
    const ull* Xb = g_xi + (size_t)b * 96 * HWp;
    int ty = tid >> 4, tx = tid & 15;
    int py = ty * 2, px = tx * 2;

    // channel-invariant load slots: 34 rows x 18 chunks (16B = 2 ull cols)
    const char* gsrc[3]; unsigned sdst[3]; int csz[3];
    int nslot = 0;
#pragma unroll
    for (int n = 0; n < 3; n++) {
        int s = tid + n * 256;
        if (s < 612) {
            int r = s / 18, ch = s % 18;
            int gy = y0 - 1 + r;
            int gx = x0 - 2 + 2 * ch;
            bool ok = (gy >= 0) && (gy < 128) && (gx >= 0) && (gx < 128);
            int goff = ok ? (gy * 128 + gx) : 0;
            gsrc[n] = (const char*)(Xb + goff);
            sdst[n] = smem_u32(&sIn[r * CROW2 + 2 * ch]);
            csz[n]  = ok ? 16 : 0;
            nslot = n + 1;
        }
    }

    // stage st loads channels 2*st, 2*st+1
    auto issue = [&](int st, int buf) {
        unsigned bofs = buf ? (unsigned)(2 * 1360 * 8) : 0u;
#pragma unroll
        for (int c2 = 0; c2 < 2; c2++) {
            size_t gofs = (size_t)(2 * st + c2) * (HWp * 8);
            unsigned so = bofs + (unsigned)(c2 * 1360 * 8);
#pragma unroll
            for (int n = 0; n < 3; n++)
                if (n < nslot) cp16(sdst[n] + so, gsrc[n] + gofs, csz[n]);
        }
        CP_COMMIT();
    };
    auto wload = [&](int st, int buf) {
        if (tid < 144) {
            int c2 = tid / 72, rr = tid % 72, co = rr / 9, k = rr % 9;
            wS[buf][c2][co * 10 + k] = g_weffP[((cob + co) * 96 + (2 * st + c2)) * 9 + k];
        }
    };

    issue(0, 0);
    wload(0, 0);

    ull acc[8][4];
#pragma unroll
    for (int i = 0; i < 8; i++)
#pragma unroll
        for (int j = 0; j < 4; j++) acc[i][j] = 0ULL;
    const ull TWO = pk2(2.f, 2.f);

    for (int st = 0; st < 48; st++) {
        int cur = st & 1;
        CP_WAIT0();
        __syncthreads();
        if (st < 47) { issue(st + 1, cur ^ 1); wload(st + 1, cur ^ 1); }

#pragma unroll
        for (int c2 = 0; c2 < 2; c2++) {
            int ci = 2 * st + c2;
            const ull* tile = sIn + (cur * 2 + c2) * 1360;
            ull rp[4][4];
#pragma unroll
            for (int i = 0; i < 4; i++)
#pragma unroll
                for (int j = 0; j < 4; j++)
                    rp[i][j] = tile[(py + i) * CROW2 + px + 1 + j];

#pragma unroll
            for (int co = 0; co < 8; co++) {
#pragma unroll
                for (int ky = 0; ky < 3; ky++)
#pragma unroll
                    for (int kx = 0; kx < 3; kx++) {
                        ull w = wS[cur][c2][co * 10 + ky * 3 + kx];
                        ffma2(acc[co][0], rp[ky][kx], w);
                        ffma2(acc[co][1], rp[ky][kx + 1], w);
                        ffma2(acc[co][2], rp[ky + 1][kx], w);
                        ffma2(acc[co][3], rp[ky + 1][kx + 1], w);
                    }
            }
            int cc = ci - cob;
            if (cc >= 0 && cc < 8) {
                ffma2(acc[cc][0], rp[1][1], TWO);
                ffma2(acc[cc][1], rp[1][2], TWO);
                ffma2(acc[cc][2], rp[2][1], TWO);
                ffma2(acc[cc][3], rp[2][2], TWO);
            }
        }
    }

    // store token-major: result = lo + hi
#pragma unroll
    for (int r = 0; r < 2; r++)
#pragma unroll
        for (int c = 0; c < 2; c++) {
            float v[8];
#pragma unroll
            for (int co = 0; co < 8; co++) {
                float lo, hi; upk(acc[co][r * 2 + c], lo, hi);
                v[co] = lo + hi;
            }
            size_t tok = (size_t)b * HWp + (size_t)(y0 + py + r) * 128 + (x0 + px + c);
            float* d = g_tokA + tok * 96 + cob;
            ((float4*)d)[0] = make_float4(v[0], v[1], v[2], v[3]);
            ((float4*)d)[1] = make_float4(v[4], v[5], v[6], v[7]);
        }
}

// ---------------- swin attention (folded), smem-staged weights ----------------
// dynamic smem: wsm ull[9216] (73728B) + tns float[8][960] (30720B) = 104448B
__global__ void __launch_bounds__(256)
k_attn(const float* __restrict__ g1, const float* __restrict__ b1) {
    extern __shared__ __align__(16) ull dynsm[];
    ull*   wsm = dynsm;                       // 9216 ull
    float* tns = (float*)(dynsm + 9216);      // [8][960]
    int tid = threadIdx.x;
    int warp = tid >> 5, lane = tid & 31;
    int tokbase = blockIdx.x * 64 + warp * 8;
    float* tnw = tns + warp * 960;

    // stage Wcomb into smem (overlapped with LN prologue)
#pragma unroll
    for (int i = 0; i < 18; i++) {
        int idx = tid + i * 256;              // < 4608
        cp16(smem_u32(wsm + 2 * idx), g_WcombP + 2 * idx, 16);
    }
    CP_COMMIT();

    float tv[8][3];
#pragma unroll
    for (int t = 0; t < 8; t++) {
        const float* tp = g_tokA + (size_t)(tokbase + t) * 96;
        float a = tp[lane], bb = tp[lane + 32], cc = tp[lane + 64];
        tv[t][0] = a; tv[t][1] = bb; tv[t][2] = cc;
        float s = a + bb + cc;
#pragma unroll
        for (int o = 16; o; o >>= 1) s += __shfl_xor_sync(0xffffffff, s, o);
        float m = s * (1.f / 96.f);
        float d0 = a - m, d1 = bb - m, d2 = cc - m;
        float q = d0 * d0 + d1 * d1 + d2 * d2;
#pragma unroll
        for (int o = 16; o; o >>= 1) q += __shfl_xor_sync(0xffffffff, q, o);
        float rstd = rsqrtf(q * (1.f / 96.f) + 1e-5f);
        tnw[lane * 10 + t]        = d0 * rstd * g1[lane]      + b1[lane];
        tnw[(lane + 32) * 10 + t] = d1 * rstd * g1[lane + 32] + b1[lane + 32];
        tnw[(lane + 64) * 10 + t] = d2 * rstd * g1[lane + 64] + b1[lane + 64];
    }
    CP_WAIT0();
    __syncthreads();

    ull acc[4][3];
#pragma unroll
    for (int p = 0; p < 4; p++) { acc[p][0] = 0; acc[p][1] = 0; acc[p][2] = 0; }
#pragma unroll 4
    for (int k = 0; k < 96; k++) {
        ull W0 = wsm[k * 96 + lane];
        ull W1 = wsm[k * 96 + lane + 32];
        ull W2 = wsm[k * 96 + lane + 64];
#pragma unroll
        for (int p = 0; p < 4; p++) {
            ull sp = *(const ull*)&tnw[k * 10 + 2 * p];
            ffma2(acc[p][0], sp, W0);
            ffma2(acc[p][1], sp, W1);
            ffma2(acc[p][2], sp, W2);
        }
    }
#pragma unroll
    for (int p = 0; p < 4; p++) {
#pragma unroll
        for (int c = 0; c < 3; c++) {
            float o0, o1; upk(acc[p][c], o0, o1);
            int ch = lane + 32 * c;
            g_tokB[(size_t)(tokbase + 2 * p) * 96 + ch]     = tv[2 * p][c]     + o0 + g_bcomb[ch];
            g_tokB[(size_t)(tokbase + 2 * p + 1) * 96 + ch] = tv[2 * p + 1][c] + o1 + g_bcomb[ch];
        }
    }
}

// ---------------- swin MLP, [ch][tok] smem, dup weights, j-halved ----------------
__global__ void __launch_bounds__(256)
k_mlp(const float* __restrict__ g2, const float* __restrict__ b2,
      const float* __restrict__ mb1, const float* __restrict__ mb2) {
    extern __shared__ float sm[];
    float* tnP = sm;            // [8][960]
    float* hsP = sm + 7680;     // [8][1920]
    int warp = threadIdx.x >> 5, lane = threadIdx.x & 31;
    int tokbase = blockIdx.x * 64 + warp * 8;
    float* tnw = tnP + warp * 960;
    float* hsw = hsP + warp * 1920;
    float tv[8][3];
#pragma unroll
    for (int t = 0; t < 8; t++) {
        const float* tp = g_tokB + (size_t)(tokbase + t) * 96;
        float a = tp[lane], bb = tp[lane + 32], cc = tp[lane + 64];
        tv[t][0] = a; tv[t][1] = bb; tv[t][2] = cc;
        float s = a + bb + cc;
#pragma unroll
        for (int o = 16; o; o >>= 1) s += __shfl_xor_sync(0xffffffff, s, o);
        float m = s * (1.f / 96.f);
        float d0 = a - m, d1 = bb - m, d2 = cc - m;
        float q = d0 * d0 + d1 * d1 + d2 * d2;
#pragma unroll
        for (int o = 16; o; o >>= 1) q += __shfl_xor_sync(0xffffffff, q, o);
        float rstd = rsqrtf(q * (1.f / 96.f) + 1e-5f);
        tnw[lane * 10 + t]        = d0 * rstd * g2[lane]      + b2[lane];
        tnw[(lane + 32) * 10 + t] = d1 * rstd * g2[lane + 32] + b2[lane + 32];
        tnw[(lane + 64) * 10 + t] = d2 * rstd * g2[lane + 64] + b2[lane + 64];
    }
    __syncwarp();
    ull oacc[4][3];
#pragma unroll
    for (int p = 0; p < 4; p++) { oacc[p][0] = 0; oacc[p][1] = 0; oacc[p][2] = 0; }

    for (int half = 0; half < 2; half++) {
        ull h[4][6];
#pragma unroll
        for (int p = 0; p < 4; p++)
#pragma unroll
            for (int r = 0; r < 6; r++) h[p][r] = 0;
        const ull* w1p = g_W1P + half * 192 + lane;
#pragma unroll 4
        for (int k = 0; k < 96; k++) {
            ull W[6];
#pragma unroll
            for (int r = 0; r < 6; r++) W[r] = w1p[k * 384 + 32 * r];
#pragma unroll
            for (int p = 0; p < 4; p++) {
                ull sp = *(const ull*)&tnw[k * 10 + 2 * p];
#pragma unroll
                for (int r = 0; r < 6; r++) ffma2(h[p][r], sp, W[r]);
            }
        }
#pragma unroll
        for (int p = 0; p < 4; p++)
#pragma unroll
            for (int r = 0; r < 6; r++) {
                int j = lane + 32 * r;
                float bias = mb1[half * 192 + j];
                float x0, x1; upk(h[p][r], x0, x1);
                hsw[j * 10 + 2 * p]     = gelu_ex(x0 + bias);
                hsw[j * 10 + 2 * p + 1] = gelu_ex(x1 + bias);
            }
        __syncwarp();
        const ull* w2p = g_W2P + (size_t)(half * 192) * 96;
#pragma unroll 4
        for (int j = 0; j < 192; j++) {
            ull U0 = w2p[j * 96 + lane];
            ull U1 = w2p[j * 96 + lane + 32];
            ull U2 = w2p[j * 96 + lane + 64];
#pragma unroll
            for (int p = 0; p < 4; p++) {
                ull hp = *(const ull*)&hsw[j * 10 + 2 * p];
                ffma2(oacc[p][0], hp, U0);
                ffma2(oacc[p][1], hp, U1);
                ffma2(oacc[p][2], hp, U2);
            }
        }
        __syncwarp();
    }
#pragma unroll
    for (int p = 0; p < 4; p++) {
#pragma unroll
        for (int c = 0; c < 3; c++) {
            float o0, o1; upk(oacc[p][c], o0, o1);
            int ch = lane + 32 * c;
            g_tokA[(size_t)(tokbase + 2 * p) * 96 + ch]     = tv[2 * p][c]     + o0 + mb2[ch];
            g_tokA[(size_t)(tokbase + 2 * p + 1) * 96 + ch] = tv[2 * p + 1][c] + o1 + mb2[ch];
        }
    }
}

// ---------------- transpose token-major -> CHW ----------------
__global__ void k_t2() {
    __shared__ float tile[32][33];
    int b = blockIdx.z, c0 = blockIdx.y * 32, p0 = blockIdx.x * 32;
    int tx = threadIdx.x, ty0 = threadIdx.y;
    for (int yy = ty0; yy < 32; yy += 8)
        tile[yy][tx] = g_tokA[(size_t)(b * HWp + p0 + yy) * 96 + c0 + tx];
    __syncthreads();
    for (int yy = ty0; yy < 32; yy += 8)
        g_cross[(size_t)(b * 96 + c0 + yy) * HWp + p0 + tx] = tile[tx][yy];
}

// ---------------- 2D DCT per (b,c) ----------------
__global__ void __launch_bounds__(256) k_dct() {
    extern __shared__ float sm[];
    float* Xs = sm;             // 16384
    float* Ys = sm + 16384;     // 16384
    int bc = blockIdx.x;
    int tid = threadIdx.x;
    const float4* src = (const float4*)(g_cross + (size_t)bc * HWp);
    float4* Xs4 = (float4*)Xs;
    for (int l = tid; l < 4096; l += 256) Xs4[l] = src[l];
    __syncthreads();

    int jq = tid & 31;
    int ig = tid >> 5;
    int j0 = 2 * jq, j2 = 64 + 2 * jq;

    for (int ii = 0; ii < 8; ii++) {
        int ip = ig + ii * 8;
        ull a00 = 0, a01 = 0, a10 = 0, a11 = 0;
        const ull* dp = g_DpD + ip * 256;
#pragma unroll 4
        for (int k = 0; k < 128; k++) {
            ull D0 = dp[2 * k], D1 = dp[2 * k + 1];
            ull xA = *(const ull*)&Xs[k * 128 + j0];
            ull xB = *(const ull*)&Xs[k * 128 + j2];
            ffma2(a00, xA, D0); ffma2(a01, xB, D0);
            ffma2(a10, xA, D1); ffma2(a11, xB, D1);
        }
        *(ull*)&Ys[(2 * ip) * 128 + j0]     = a00;
        *(ull*)&Ys[(2 * ip) * 128 + j2]     = a01;
        *(ull*)&Ys[(2 * ip + 1) * 128 + j0] = a10;
        *(ull*)&Ys[(2 * ip + 1) * 128 + j2] = a11;
    }
    __syncthreads();

    ull acc[8][4];
#pragma unroll
    for (int ii = 0; ii < 8; ii++)
#pragma unroll
        for (int q = 0; q < 4; q++) acc[ii][q] = 0;
#pragma unroll 2
    for (int k = 0; k < 128; k++) {
        ull dtA = *(const ull*)&g_DT[k * 128 + j0];
        ull dtB = *(const ull*)&g_DT[k * 128 + j2];
#pragma unroll
        for (int ii = 0; ii < 8; ii++) {
            int ip = ig + ii * 8;
            float y0 = Ys[(2 * ip) * 128 + k];
            float y1 = Ys[(2 * ip + 1) * 128 + k];
            ull Y0 = pk2(y0, y0), Y1 = pk2(y1, y1);
            ffma2(acc[ii][0], dtA, Y0); ffma2(acc[ii][1], dtB, Y0);
            ffma2(acc[ii][2], dtA, Y1); ffma2(acc[ii][3], dtB, Y1);
        }
    }
    float* dst = g_dct + (size_t)bc * HWp;
#pragma unroll
    for (int ii = 0; ii < 8; ii++) {
        int ip = ig + ii * 8;
        *(ull*)&dst[(2 * ip) * 128 + j0]     = acc[ii][0];
        *(ull*)&dst[(2 * ip) * 128 + j2]     = acc[ii][1];
        *(ull*)&dst[(2 * ip + 1) * 128 + j0] = acc[ii][2];
        *(ull*)&dst[(2 * ip + 1) * 128 + j2] = acc[ii][3];
    }
}

// ---------------- channel-mean |dct| (float4) ----------------
__global__ void k_energy() {
    int g = blockIdx.x * blockDim.x + threadIdx.x;   // 16384
    int b = g >> 12, p4 = g & 4095;
    const float4* base = (const float4*)(g_dct + (size_t)b * 96 * HWp) + p4;
    float4 s = make_float4(0.f, 0.f, 0.f, 0.f);
    for (int c = 0; c < 96; c++) {
        float4 v = base[(size_t)c * 4096];
        s.x += fabsf(v.x); s.y += fabsf(v.y); s.z += fabsf(v.z); s.w += fabsf(v.w);
    }
    float inv = 1.f / 96.f;
    s.x *= inv; s.y *= inv; s.z *= inv; s.w *= inv;
    ((float4*)(g_energy + b * HWp))[p4] = s;
}

// ---------------- top-96 via histogram threshold + rank sort ----------------
__global__ void __launch_bounds__(256)
k_topk(const float* __restrict__ fw1, const float* __restrict__ fb1,
       const float* __restrict__ fw2, const float* __restrict__ fb2) {
    extern __shared__ float e[];                 // 16384 floats
    int* hist = (int*)(e + 16384);               // 4096 ints (reused as cand)
    __shared__ int csum[256];
    __shared__ int s_T, s_cnt;
    __shared__ float tk[96];
    __shared__ float hh[24];
    int b = blockIdx.x, tid = threadIdx.x;

    const float4* src = (const float4*)(g_energy + b * HWp);
    float4* e4 = (float4*)e;
    for (int l = tid; l < 4096; l += 256) e4[l] = src[l];
    for (int l = tid; l < 4096; l += 256) hist[l] = 0;
    __syncthreads();
    for (int l = tid; l < 16384; l += 256) {
        int key = (int)(__float_as_uint(e[l]) >> 19);
        atomicAdd(&hist[key], 1);
    }
    __syncthreads();
    {
        int s = 0;
#pragma unroll
        for (int k = 0; k < 16; k++) s += hist[tid * 16 + k];
        csum[tid] = s;
    }
    __syncthreads();
    if (tid == 0) {
        int run = 0, cstar = 0;
        for (int c = 255; c >= 0; c--) {
            if (run + csum[c] >= 96) { cstar = c; break; }
            run += csum[c];
        }
        int T = cstar * 16;
        for (int k = 15; k >= 0; k--) {
            int bin = cstar * 16 + k;
            if (run + hist[bin] >= 96) { T = bin; break; }
            run += hist[bin];
        }
        s_T = T; s_cnt = 0;
    }
    __syncthreads();
    int T = s_T;
    float* cand = (float*)hist;
    __syncthreads();
    for (int l = tid; l < 16384; l += 256) {
        float v = e[l];
        if ((int)(__float_as_uint(v) >> 19) >= T) {
            int pos = atomicAdd(&s_cnt, 1);
            if (pos < 4096) cand[pos] = v;
        }
    }
    __syncthreads();
    int M = s_cnt; if (M > 4096) M = 4096;
    for (int i = tid; i < M; i += 256) {
        float v = cand[i];
        int r = 0;
        for (int j = 0; j < M; j++) {
            float u = cand[j];
            r += (u > v) || (u == v && j < i);
        }
        if (r < 96) tk[r] = v;
    }
    __syncthreads();
    if (tid < 24) {
        float s = fb1[tid];
        for (int k = 0; k < 96; k++) s += tk[k] * fw1[tid * 96 + k];
        hh[tid] = fmaxf(s, 0.f);
    }
    __syncthreads();
    if (tid == 0) {
        float a = fb2[0];
        for (int j = 0; j < 24; j++) a += hh[j] * fw2[j];
        g_scale[b] = 1.f + 1.f / (1.f + expf(-a));
    }
}

// ---------------- epilogue (float4) ----------------
__global__ void k_final(const float* __restrict__ x1, const float* __restrict__ x2,
                        float* __restrict__ out) {
    int i = blockIdx.x * blockDim.x + threadIdx.x;   // NTOT/4
    float s = g_scale[i / (96 * HWp / 4)];
    float4 c = ((const float4*)g_cross)[i];
    float4 a = ((const float4*)x1)[i];
    float4 b = ((const float4*)x2)[i];
    float4 o1, o2;
    o1.x = a.x + s * c.x; o1.y = a.y + s * c.y; o1.z = a.z + s * c.z; o1.w = a.w + s * c.w;
    o2.x = b.x + s * c.x; o2.y = b.y + s * c.y; o2.z = b.z + s * c.z; o2.w = b.w + s * c.w;
    ((float4*)out)[i]            = o1;
    ((float4*)out)[NTOT / 4 + i] = o2;
}

extern "C" void kernel_launch(void* const* d_in, const int* in_sizes, int n_in,
                              void* d_out, int out_size) {
    const float* x1     = (const float*)d_in[0];
    const float* x2     = (const float*)d_in[1];
    const float* w_tx1  = (const float*)d_in[2];
    const float* lm1    = (const float*)d_in[3];
    const float* theta1 = (const float*)d_in[4];
    const float* w_tx2  = (const float*)d_in[5];
    const float* lm2    = (const float*)d_in[6];
    const float* theta2 = (const float*)d_in[7];
    const float* ln1_g  = (const float*)d_in[8];
    const float* ln1_b  = (const float*)d_in[9];
    const float* qkv_w  = (const float*)d_in[10];
    const float* qkv_b  = (const float*)d_in[11];
    const float* proj_w = (const float*)d_in[12];
    const float* proj_b = (const float*)d_in[13];
    const float* ln2_g  = (const float*)d_in[14];
    const float* ln2_b  = (const float*)d_in[15];
    const float* mlp_w1 = (const float*)d_in[16];
    const float* mlp_b1 = (const float*)d_in[17];
    const float* mlp_w2 = (const float*)d_in[18];
    const float* mlp_b2 = (const float*)d_in[19];
    const float* fc_w1  = (const float*)d_in[20];
    const float* fc_b1  = (const float*)d_in[21];
    const float* fc_w2  = (const float*)d_in[22];
    const float* fc_b2  = (const float*)d_in[23];
    float* out = (float*)d_out;

    cudaFuncSetAttribute(k_conv, cudaFuncAttributeMaxDynamicSharedMemorySize, 87040);
    cudaFuncSetAttribute(k_attn, cudaFuncAttributeMaxDynamicSharedMemorySize, 104448);
    cudaFuncSetAttribute(k_mlp,  cudaFuncAttributeMaxDynamicSharedMemorySize, 92160);
    cudaFuncSetAttribute(k_dct,  cudaFuncAttributeMaxDynamicSharedMemorySize, 131072);
    cudaFuncSetAttribute(k_topk, cudaFuncAttributeMaxDynamicSharedMemorySize, 81920);

    // slot 4 (ncu capture) = k_conv
    k_ilv<<<NTOT / 4 / 256, 256>>>(x1, x2);
    k_weffP<<<36, 256>>>(w_tx1, lm1, theta1, w_tx2, lm2, theta2);
    k_prep2<<<241, 256>>>(qkv_w, qkv_b, proj_w, proj_b, mlp_w1, mlp_w2);
    k_conv<<<dim3(16, 12, 4), 256, 87040>>>();
    k_attn<<<1024, 256, 104448>>>(ln1_g, ln1_b);
    k_mlp<<<1024, 256, 92160>>>(ln2_g, ln2_b, mlp_b1, mlp_b2);
    k_init_dct<<<64, 256>>>();
    k_t2<<<dim3(512, 3, 4), dim3(32, 8)>>>();
    k_dct<<<384, 256, 131072>>>();
    k_energy<<<64, 256>>>();
    k_topk<<<4, 256, 81920>>>(fc_w1, fc_b1, fc_w2, fc_b2);
    k_final<<<NTOT / 4 / 256, 256>>>(x1, x2, out);
}

// round 7
// speedup vs baseline: 1.0908x; 1.0027x over previous
#include <cuda_runtime.h>
#include <math.h>

#define Bq   4
#define Cc   96
#define HWp  16384
#define NTOT (Bq*Cc*HWp)          // 6291456
#define CROW2 40                   // conv smem row stride (ull)

typedef unsigned long long ull;

__device__ __forceinline__ ull pk2(float lo, float hi) {
    ull r; asm("mov.b64 %0,{%1,%2};" : "=l"(r) : "f"(lo), "f"(hi)); return r;
}
__device__ __forceinline__ void upk(ull v, float& lo, float& hi) {
    asm("mov.b64 {%0,%1},%2;" : "=f"(lo), "=f"(hi) : "l"(v));
}
__device__ __forceinline__ void ffma2(ull& d, ull a, ull b) {
    asm("fma.rn.f32x2 %0,%1,%2,%0;" : "+l"(d) : "l"(a), "l"(b));
}
__device__ __forceinline__ float gelu_ex(float x) {
    return 0.5f * x * (1.f + erff(x * 0.70710678118654752f));
}
__device__ __forceinline__ unsigned smem_u32(const void* p) {
    return (unsigned)__cvta_generic_to_shared(p);
}
__device__ __forceinline__ void cp16(unsigned dst, const void* src, int n) {
    asm volatile("cp.async.cg.shared.global [%0],[%1],16,%2;" :: "r"(dst), "l"(src), "r"(n));
}
#define CP_COMMIT() asm volatile("cp.async.commit_group;")
#define CP_WAIT0()  asm volatile("cp.async.wait_group 0;")

// ---------------- device scratch ----------------
__device__ ull   g_xi[NTOT];        // interleaved (x1,x2) pairs, CHW
__device__ ull   g_weffP[96*96*9];  // (w1eff,w2eff) pairs
__device__ float g_DT[128*128];
__device__ ull   g_DpD[128*128];    // dup pairs for DCT stage-1
__device__ ull   g_WcombP[96*96];   // dup
__device__ float g_bcomb[96];
__device__ ull   g_W1P[96*384];     // dup, [k*384+j]
__device__ ull   g_W2P[384*96];     // dup, [j*96+i]
__device__ float g_tokA[NTOT];
__device__ float g_tokB[NTOT];
__device__ float g_cross[NTOT];
__device__ float g_dct[NTOT];
__device__ float g_energy[Bq*HWp];
__device__ float g_scale[Bq];

// ---------------- interleave x1,x2 into pair array ----------------
__global__ void k_ilv(const float* __restrict__ x1, const float* __restrict__ x2) {
    int g = blockIdx.x * blockDim.x + threadIdx.x;   // NTOT/4
    float4 a = ((const float4*)x1)[g];
    float4 b = ((const float4*)x2)[g];
    ((float4*)g_xi)[2 * g]     = make_float4(a.x, b.x, a.y, b.y);
    ((float4*)g_xi)[2 * g + 1] = make_float4(a.z, b.z, a.w, b.w);
}

// ---------------- LDC effective weights, packed (w1,w2) ----------------
__global__ void k_weffP(const float* __restrict__ w1, const float* __restrict__ lm1,
                        const float* __restrict__ th1,
                        const float* __restrict__ w2, const float* __restrict__ lm2,
                        const float* __restrict__ th2) {
    int t = blockIdx.x * 256 + threadIdx.x;
    if (t >= 96 * 96) return;
    const float* ws1 = w1 + t * 9;
    const float* ws2 = w2 + t * 9;
    float s1 = 0.f, s2 = 0.f;
#pragma unroll
    for (int k = 0; k < 9; k++) { s1 += ws1[k]; s2 += ws2[k]; }
    float sc1 = 1.f - th1[0] * lm1[t] * s1;
    float sc2 = 1.f - th2[0] * lm2[t] * s2;
    ull* o = g_weffP + t * 9;
#pragma unroll
    for (int k = 0; k < 9; k++) o[k] = pk2(ws1[k], ws2[k]);
    o[4] = pk2(ws1[4] * sc1, ws2[4] * sc2);
}

// ---------------- init: DCT-II matrices ----------------
__global__ void k_init_dct() {
    int t = blockIdx.x * blockDim.x + threadIdx.x;   // 16384
    int k = t >> 7, i = t & 127;
    float arg = (float)((2 * i + 1) * k) * (1.0f / 256.0f);
    float v = cospif(arg) * 0.125f;
    if (k == 0) v *= 0.70710678118654752440f;
    g_DT[i * 128 + k] = v;
    g_DpD[((k >> 1) * 128 + i) * 2 + (k & 1)] = pk2(v, v);
}

// ---------------- prep: Wcomb dup, bcomb, MLP dup transposes ----------------
__global__ void k_prep2(const float* __restrict__ qkv_w, const float* __restrict__ qkv_b,
                        const float* __restrict__ proj_w, const float* __restrict__ proj_b,
                        const float* __restrict__ w1, const float* __restrict__ w2) {
    int blk = blockIdx.x, tid = threadIdx.x;
    if (blk < 96) {
        if (tid < 96) {
            float s = 0.f;
            for (int m = 0; m < 96; m++)
                s += proj_w[blk * 96 + m] * qkv_w[(192 + m) * 96 + tid];
            g_WcombP[tid * 96 + blk] = pk2(s, s);
        }
    } else if (blk == 96) {
        if (tid < 96) {
            float s = proj_b[tid];
            for (int m = 0; m < 96; m++)
                s += proj_w[tid * 96 + m] * qkv_b[192 + m];
            g_bcomb[tid] = s;
        }
    } else {
        int t = (blk - 97) * 256 + tid;
        if (t < 96 * 384) {
            { int k = t / 384, j = t % 384; float v = w1[j * 96 + k]; g_W1P[t] = pk2(v, v); }
            { int k = t / 96,  i = t % 96;  float v = w2[i * 384 + k]; g_W2P[t] = pk2(v, v); }
        }
    }
}

// ---------------- fused double conv + residual, 2-channel pipeline stages ----------------
// dynamic smem: sIn[2 stages][2 ch][34*CROW2] ull = 87040 B
__global__ void __launch_bounds__(256, 2)
k_conv() {
    extern __shared__ __align__(16) ull sIn[];      // [st][c2][1360]
    __shared__ __align__(16) ull wS[2][2][80];      // [st][c2][co*10+k]
    int tid = threadIdx.x;
    int b   = blockIdx.z;
    int cob = blockIdx.y * 8;
    int bt  = blockIdx.x;
    int y0  = (bt >> 2) * 32, x0 = (bt & 3) * 32;
    const ull* Xb = g_xi + (size_t)b * 96 * HWp;
    int ty = tid >> 4, tx = tid & 15;
    int py = ty * 2, px = tx * 2;

    // channel-invariant load slots: 34 rows x 18 chunks (16B = 2 ull cols)
    const char* gsrc[3]; unsigned sdst[3]; int csz[3];
    int nslot = 0;
#pragma unroll
    for (int n = 0; n < 3; n++) {
        int s = tid + n * 256;
        if (s < 612) {
            int r = s / 18, ch = s % 18;
            int gy = y0 - 1 + r;
            int gx = x0 - 2 + 2 * ch;
            bool ok = (gy >= 0) && (gy < 128) && (gx >= 0) && (gx < 128);
            int goff = ok ? (gy * 128 + gx) : 0;
            gsrc[n] = (const char*)(Xb + goff);
            sdst[n] = smem_u32(&sIn[r * CROW2 + 2 * ch]);
            csz[n]  = ok ? 16 : 0;
            nslot = n + 1;
        }
    }

    // stage st loads channels 2*st, 2*st+1
    auto issue = [&](int st, int buf) {
        unsigned bofs = buf ? (unsigned)(2 * 1360 * 8) : 0u;
#pragma unroll
        for (int c2 = 0; c2 < 2; c2++) {
            size_t gofs = (size_t)(2 * st + c2) * (HWp * 8);
            unsigned so = bofs + (unsigned)(c2 * 1360 * 8);
#pragma unroll
            for (int n = 0; n < 3; n++)
                if (n < nslot) cp16(sdst[n] + so, gsrc[n] + gofs, csz[n]);
        }
        CP_COMMIT();
    };
    auto wload = [&](int st, int buf) {
        if (tid < 144) {
            int c2 = tid / 72, rr = tid % 72, co = rr / 9, k = rr % 9;
            wS[buf][c2][co * 10 + k] = g_weffP[((cob + co) * 96 + (2 * st + c2)) * 9 + k];
        }
    };

    issue(0, 0);
    wload(0, 0);

    ull acc[8][4];
#pragma unroll
    for (int i = 0; i < 8; i++)
#pragma unroll
        for (int j = 0; j < 4; j++) acc[i][j] = 0ULL;
    const ull TWO = pk2(2.f, 2.f);

    for (int st = 0; st < 48; st++) {
        int cur = st & 1;
        CP_WAIT0();
        __syncthreads();
        if (st < 47) { issue(st + 1, cur ^ 1); wload(st + 1, cur ^ 1); }

#pragma unroll
        for (int c2 = 0; c2 < 2; c2++) {
            int ci = 2 * st + c2;
            const ull* tile = sIn + (cur * 2 + c2) * 1360;
            ull rp[4][4];
#pragma unroll
            for (int i = 0; i < 4; i++)
#pragma unroll
                for (int j = 0; j < 4; j++)
                    rp[i][j] = tile[(py + i) * CROW2 + px + 1 + j];

#pragma unroll
            for (int co = 0; co < 8; co++) {
#pragma unroll
                for (int ky = 0; ky < 3; ky++)
#pragma unroll
                    for (int kx = 0; kx < 3; kx++) {
                        ull w = wS[cur][c2][co * 10 + ky * 3 + kx];
                        ffma2(acc[co][0], rp[ky][kx], w);
                        ffma2(acc[co][1], rp[ky][kx + 1], w);
                        ffma2(acc[co][2], rp[ky + 1][kx], w);
                        ffma2(acc[co][3], rp[ky + 1][kx + 1], w);
                    }
            }
            int cc = ci - cob;
            if (cc >= 0 && cc < 8) {
                ffma2(acc[cc][0], rp[1][1], TWO);
                ffma2(acc[cc][1], rp[1][2], TWO);
                ffma2(acc[cc][2], rp[2][1], TWO);
                ffma2(acc[cc][3], rp[2][2], TWO);
            }
        }
    }

    // store token-major: result = lo + hi
#pragma unroll
    for (int r = 0; r < 2; r++)
#pragma unroll
        for (int c = 0; c < 2; c++) {
            float v[8];
#pragma unroll
            for (int co = 0; co < 8; co++) {
                float lo, hi; upk(acc[co][r * 2 + c], lo, hi);
                v[co] = lo + hi;
            }
            size_t tok = (size_t)b * HWp + (size_t)(y0 + py + r) * 128 + (x0 + px + c);
            float* d = g_tokA + tok * 96 + cob;
            ((float4*)d)[0] = make_float4(v[0], v[1], v[2], v[3]);
            ((float4*)d)[1] = make_float4(v[4], v[5], v[6], v[7]);
        }
}

// ---------------- swin attention (folded), smem-staged weights ----------------
// dynamic smem: wsm ull[9216] (73728B) + tns float[8][960] (30720B) = 104448B
__global__ void __launch_bounds__(256)
k_attn(const float* __restrict__ g1, const float* __restrict__ b1) {
    extern __shared__ __align__(16) ull dynsm[];
    ull*   wsm = dynsm;                       // 9216 ull
    float* tns = (float*)(dynsm + 9216);      // [8][960]
    int tid = threadIdx.x;
    int warp = tid >> 5, lane = tid & 31;
    int tokbase = blockIdx.x * 64 + warp * 8;
    float* tnw = tns + warp * 960;

    // stage Wcomb into smem (overlapped with LN prologue)
#pragma unroll
    for (int i = 0; i < 18; i++) {
        int idx = tid + i * 256;              // < 4608
        cp16(smem_u32(wsm + 2 * idx), g_WcombP + 2 * idx, 16);
    }
    CP_COMMIT();

    float tv[8][3];
#pragma unroll
    for (int t = 0; t < 8; t++) {
        const float* tp = g_tokA + (size_t)(tokbase + t) * 96;
        float a = tp[lane], bb = tp[lane + 32], cc = tp[lane + 64];
        tv[t][0] = a; tv[t][1] = bb; tv[t][2] = cc;
        float s = a + bb + cc;
#pragma unroll
        for (int o = 16; o; o >>= 1) s += __shfl_xor_sync(0xffffffff, s, o);
        float m = s * (1.f / 96.f);
        float d0 = a - m, d1 = bb - m, d2 = cc - m;
        float q = d0 * d0 + d1 * d1 + d2 * d2;
#pragma unroll
        for (int o = 16; o; o >>= 1) q += __shfl_xor_sync(0xffffffff, q, o);
        float rstd = rsqrtf(q * (1.f / 96.f) + 1e-5f);
        tnw[lane * 10 + t]        = d0 * rstd * g1[lane]      + b1[lane];
        tnw[(lane + 32) * 10 + t] = d1 * rstd * g1[lane + 32] + b1[lane + 32];
        tnw[(lane + 64) * 10 + t] = d2 * rstd * g1[lane + 64] + b1[lane + 64];
    }
    CP_WAIT0();
    __syncthreads();

    ull acc[4][3];
#pragma unroll
    for (int p = 0; p < 4; p++) { acc[p][0] = 0; acc[p][1] = 0; acc[p][2] = 0; }
#pragma unroll 4
    for (int k = 0; k < 96; k++) {
        ull W0 = wsm[k * 96 + lane];
        ull W1 = wsm[k * 96 + lane + 32];
        ull W2 = wsm[k * 96 + lane + 64];
#pragma unroll
        for (int p = 0; p < 4; p++) {
            ull sp = *(const ull*)&tnw[k * 10 + 2 * p];
            ffma2(acc[p][0], sp, W0);
            ffma2(acc[p][1], sp, W1);
            ffma2(acc[p][2], sp, W2);
        }
    }
#pragma unroll
    for (int p = 0; p < 4; p++) {
#pragma unroll
        for (int c = 0; c < 3; c++) {
            float o0, o1; upk(acc[p][c], o0, o1);
            int ch = lane + 32 * c;
            g_tokB[(size_t)(tokbase + 2 * p) * 96 + ch]     = tv[2 * p][c]     + o0 + g_bcomb[ch];
            g_tokB[(size_t)(tokbase + 2 * p + 1) * 96 + ch] = tv[2 * p + 1][c] + o1 + g_bcomb[ch];
        }
    }
}

// ---------------- swin MLP, [ch][tok] smem, dup weights, j-halved ----------------
__global__ void __launch_bounds__(256)
k_mlp(const float* __restrict__ g2, const float* __restrict__ b2,
      const float* __restrict__ mb1, const float* __restrict__ mb2) {
    extern __shared__ float sm[];
    float* tnP = sm;            // [8][960]
    float* hsP = sm + 7680;     // [8][1920]
    int warp = threadIdx.x >> 5, lane = threadIdx.x & 31;
    int tokbase = blockIdx.x * 64 + warp * 8;
    float* tnw = tnP + warp * 960;
    float* hsw = hsP + warp * 1920;
    float tv[8][3];
#pragma unroll
    for (int t = 0; t < 8; t++) {
        const float* tp = g_tokB + (size_t)(tokbase + t) * 96;
        float a = tp[lane], bb = tp[lane + 32], cc = tp[lane + 64];
        tv[t][0] = a; tv[t][1] = bb; tv[t][2] = cc;
        float s = a + bb + cc;
#pragma unroll
        for (int o = 16; o; o >>= 1) s += __shfl_xor_sync(0xffffffff, s, o);
        float m = s * (1.f / 96.f);
        float d0 = a - m, d1 = bb - m, d2 = cc - m;
        float q = d0 * d0 + d1 * d1 + d2 * d2;
#pragma unroll
        for (int o = 16; o; o >>= 1) q += __shfl_xor_sync(0xffffffff, q, o);
        float rstd = rsqrtf(q * (1.f / 96.f) + 1e-5f);
        tnw[lane * 10 + t]        = d0 * rstd * g2[lane]      + b2[lane];
        tnw[(lane + 32) * 10 + t] = d1 * rstd * g2[lane + 32] + b2[lane + 32];
        tnw[(lane + 64) * 10 + t] = d2 * rstd * g2[lane + 64] + b2[lane + 64];
    }
    __syncwarp();
    ull oacc[4][3];
#pragma unroll
    for (int p = 0; p < 4; p++) { oacc[p][0] = 0; oacc[p][1] = 0; oacc[p][2] = 0; }

    for (int half = 0; half < 2; half++) {
        ull h[4][6];
#pragma unroll
        for (int p = 0; p < 4; p++)
#pragma unroll
            for (int r = 0; r < 6; r++) h[p][r] = 0;
        const ull* w1p = g_W1P + half * 192 + lane;
#pragma unroll 4
        for (int k = 0; k < 96; k++) {
            ull W[6];
#pragma unroll
            for (int r = 0; r < 6; r++) W[r] = w1p[k * 384 + 32 * r];
#pragma unroll
            for (int p = 0; p < 4; p++) {
                ull sp = *(const ull*)&tnw[k * 10 + 2 * p];
#pragma unroll
                for (int r = 0; r < 6; r++) ffma2(h[p][r], sp, W[r]);
            }
        }
#pragma unroll
        for (int p = 0; p < 4; p++)
#pragma unroll
            for (int r = 0; r < 6; r++) {
                int j = lane + 32 * r;
                float bias = mb1[half * 192 + j];
                float x0, x1; upk(h[p][r], x0, x1);
                hsw[j * 10 + 2 * p]     = gelu_ex(x0 + bias);
                hsw[j * 10 + 2 * p + 1] = gelu_ex(x1 + bias);
            }
        __syncwarp();
        const ull* w2p = g_W2P + (size_t)(half * 192) * 96;
#pragma unroll 4
        for (int j = 0; j < 192; j++) {
            ull U0 = w2p[j * 96 + lane];
            ull U1 = w2p[j * 96 + lane + 32];
            ull U2 = w2p[j * 96 + lane + 64];
#pragma unroll
            for (int p = 0; p < 4; p++) {
                ull hp = *(const ull*)&hsw[j * 10 + 2 * p];
                ffma2(oacc[p][0], hp, U0);
                ffma2(oacc[p][1], hp, U1);
                ffma2(oacc[p][2], hp, U2);
            }
        }
        __syncwarp();
    }
#pragma unroll
    for (int p = 0; p < 4; p++) {
#pragma unroll
        for (int c = 0; c < 3; c++) {
            float o0, o1; upk(oacc[p][c], o0, o1);
            int ch = lane + 32 * c;
            g_tokA[(size_t)(tokbase + 2 * p) * 96 + ch]     = tv[2 * p][c]     + o0 + mb2[ch];
            g_tokA[(size_t)(tokbase + 2 * p + 1) * 96 + ch] = tv[2 * p + 1][c] + o1 + mb2[ch];
        }
    }
}

// ---------------- transpose token-major -> CHW ----------------
__global__ void k_t2() {
    __shared__ float tile[32][33];
    int b = blockIdx.z, c0 = blockIdx.y * 32, p0 = blockIdx.x * 32;
    int tx = threadIdx.x, ty0 = threadIdx.y;
    for (int yy = ty0; yy < 32; yy += 8)
        tile[yy][tx] = g_tokA[(size_t)(b * HWp + p0 + yy) * 96 + c0 + tx];
    __syncthreads();
    for (int yy = ty0; yy < 32; yy += 8)
        g_cross[(size_t)(b * 96 + c0 + yy) * HWp + p0 + tx] = tile[tx][yy];
}

// ---------------- 2D DCT per (b,c) ----------------
__global__ void __launch_bounds__(256) k_dct() {
    extern __shared__ float sm[];
    float* Xs = sm;             // 16384
    float* Ys = sm + 16384;     // 16384
    int bc = blockIdx.x;
    int tid = threadIdx.x;
    const float4* src = (const float4*)(g_cross + (size_t)bc * HWp);
    float4* Xs4 = (float4*)Xs;
    for (int l = tid; l < 4096; l += 256) Xs4[l] = src[l];
    __syncthreads();

    int jq = tid & 31;
    int ig = tid >> 5;
    int j0 = 2 * jq, j2 = 64 + 2 * jq;

    for (int ii = 0; ii < 8; ii++) {
        int ip = ig + ii * 8;
        ull a00 = 0, a01 = 0, a10 = 0, a11 = 0;
        const ull* dp = g_DpD + ip * 256;
#pragma unroll 4
        for (int k = 0; k < 128; k++) {
            ull D0 = dp[2 * k], D1 = dp[2 * k + 1];
            ull xA = *(const ull*)&Xs[k * 128 + j0];
            ull xB = *(const ull*)&Xs[k * 128 + j2];
            ffma2(a00, xA, D0); ffma2(a01, xB, D0);
            ffma2(a10, xA, D1); ffma2(a11, xB, D1);
        }
        *(ull*)&Ys[(2 * ip) * 128 + j0]     = a00;
        *(ull*)&Ys[(2 * ip) * 128 + j2]     = a01;
        *(ull*)&Ys[(2 * ip + 1) * 128 + j0] = a10;
        *(ull*)&Ys[(2 * ip + 1) * 128 + j2] = a11;
    }
    __syncthreads();

    ull acc[8][4];
#pragma unroll
    for (int ii = 0; ii < 8; ii++)
#pragma unroll
        for (int q = 0; q < 4; q++) acc[ii][q] = 0;
#pragma unroll 2
    for (int k = 0; k < 128; k++) {
        ull dtA = *(const ull*)&g_DT[k * 128 + j0];
        ull dtB = *(const ull*)&g_DT[k * 128 + j2];
#pragma unroll
        for (int ii = 0; ii < 8; ii++) {
            int ip = ig + ii * 8;
            float y0 = Ys[(2 * ip) * 128 + k];
            float y1 = Ys[(2 * ip + 1) * 128 + k];
            ull Y0 = pk2(y0, y0), Y1 = pk2(y1, y1);
            ffma2(acc[ii][0], dtA, Y0); ffma2(acc[ii][1], dtB, Y0);
            ffma2(acc[ii][2], dtA, Y1); ffma2(acc[ii][3], dtB, Y1);
        }
    }
    float* dst = g_dct + (size_t)bc * HWp;
#pragma unroll
    for (int ii = 0; ii < 8; ii++) {
        int ip = ig + ii * 8;
        *(ull*)&dst[(2 * ip) * 128 + j0]     = acc[ii][0];
        *(ull*)&dst[(2 * ip) * 128 + j2]     = acc[ii][1];
        *(ull*)&dst[(2 * ip + 1) * 128 + j0] = acc[ii][2];
        *(ull*)&dst[(2 * ip + 1) * 128 + j2] = acc[ii][3];
    }
}

// ---------------- channel-mean |dct| (float4) ----------------
__global__ void k_energy() {
    int g = blockIdx.x * blockDim.x + threadIdx.x;   // 16384
    int b = g >> 12, p4 = g & 4095;
    const float4* base = (const float4*)(g_dct + (size_t)b * 96 * HWp) + p4;
    float4 s = make_float4(0.f, 0.f, 0.f, 0.f);
    for (int c = 0; c < 96; c++) {
        float4 v = base[(size_t)c * 4096];
        s.x += fabsf(v.x); s.y += fabsf(v.y); s.z += fabsf(v.z); s.w += fabsf(v.w);
    }
    float inv = 1.f / 96.f;
    s.x *= inv; s.y *= inv; s.z *= inv; s.w *= inv;
    ((float4*)(g_energy + b * HWp))[p4] = s;
}

// ---------------- top-96 via histogram threshold + rank sort ----------------
__global__ void __launch_bounds__(256)
k_topk(const float* __restrict__ fw1, const float* __restrict__ fb1,
       const float* __restrict__ fw2, const float* __restrict__ fb2) {
    extern __shared__ float e[];                 // 16384 floats
    int* hist = (int*)(e + 16384);               // 4096 ints (reused as cand)
    __shared__ int csum[256];
    __shared__ int s_T, s_cnt;
    __shared__ float tk[96];
    __shared__ float hh[24];
    int b = blockIdx.x, tid = threadIdx.x;

    const float4* src = (const float4*)(g_energy + b * HWp);
    float4* e4 = (float4*)e;
    for (int l = tid; l < 4096; l += 256) e4[l] = src[l];
    for (int l = tid; l < 4096; l += 256) hist[l] = 0;
    __syncthreads();
    for (int l = tid; l < 16384; l += 256) {
        int key = (int)(__float_as_uint(e[l]) >> 19);
        atomicAdd(&hist[key], 1);
    }
    __syncthreads();
    {
        int s = 0;
#pragma unroll
        for (int k = 0; k < 16; k++) s += hist[tid * 16 + k];
        csum[tid] = s;
    }
    __syncthreads();
    if (tid == 0) {
        int run = 0, cstar = 0;
        for (int c = 255; c >= 0; c--) {
            if (run + csum[c] >= 96) { cstar = c; break; }
            run += csum[c];
        }
        int T = cstar * 16;
        for (int k = 15; k >= 0; k--) {
            int bin = cstar * 16 + k;
            if (run + hist[bin] >= 96) { T = bin; break; }
            run += hist[bin];
        }
        s_T = T; s_cnt = 0;
    }
    __syncthreads();
    int T = s_T;
    float* cand = (float*)hist;
    __syncthreads();
    for (int l = tid; l < 16384; l += 256) {
        float v = e[l];
        if ((int)(__float_as_uint(v) >> 19) >= T) {
            int pos = atomicAdd(&s_cnt, 1);
            if (pos < 4096) cand[pos] = v;
        }
    }
    __syncthreads();
    int M = s_cnt; if (M > 4096) M = 4096;
    for (int i = tid; i < M; i += 256) {
        float v = cand[i];
        int r = 0;
        for (int j = 0; j < M; j++) {
            float u = cand[j];
            r += (u > v) || (u == v && j < i);
        }
        if (r < 96) tk[r] = v;
    }
    __syncthreads();
    if (tid < 24) {
        float s = fb1[tid];
        for (int k = 0; k < 96; k++) s += tk[k] * fw1[tid * 96 + k];
        hh[tid] = fmaxf(s, 0.f);
    }
    __syncthreads();
    if (tid == 0) {
        float a = fb2[0];
        for (int j = 0; j < 24; j++) a += hh[j] * fw2[j];
        g_scale[b] = 1.f + 1.f / (1.f + expf(-a));
    }
}

// ---------------- epilogue (float4) ----------------
__global__ void k_final(const float* __restrict__ x1, const float* __restrict__ x2,
                        float* __restrict__ out) {
    int i = blockIdx.x * blockDim.x + threadIdx.x;   // NTOT/4
    float s = g_scale[i / (96 * HWp / 4)];
    float4 c = ((const float4*)g_cross)[i];
    float4 a = ((const float4*)x1)[i];
    float4 b = ((const float4*)x2)[i];
    float4 o1, o2;
    o1.x = a.x + s * c.x; o1.y = a.y + s * c.y; o1.z = a.z + s * c.z; o1.w = a.w + s * c.w;
    o2.x = b.x + s * c.x; o2.y = b.y + s * c.y; o2.z = b.z + s * c.z; o2.w = b.w + s * c.w;
    ((float4*)out)[i]            = o1;
    ((float4*)out)[NTOT / 4 + i] = o2;
}

extern "C" void kernel_launch(void* const* d_in, const int* in_sizes, int n_in,
                              void* d_out, int out_size) {
    const float* x1     = (const float*)d_in[0];
    const float* x2     = (const float*)d_in[1];
    const float* w_tx1  = (const float*)d_in[2];
    const float* lm1    = (const float*)d_in[3];
    const float* theta1 = (const float*)d_in[4];
    const float* w_tx2  = (const float*)d_in[5];
    const float* lm2    = (const float*)d_in[6];
    const float* theta2 = (const float*)d_in[7];
    const float* ln1_g  = (const float*)d_in[8];
    const float* ln1_b  = (const float*)d_in[9];
    const float* qkv_w  = (const float*)d_in[10];
    const float* qkv_b  = (const float*)d_in[11];
    const float* proj_w = (const float*)d_in[12];
    const float* proj_b = (const float*)d_in[13];
    const float* ln2_g  = (const float*)d_in[14];
    const float* ln2_b  = (const float*)d_in[15];
    const float* mlp_w1 = (const float*)d_in[16];
    const float* mlp_b1 = (const float*)d_in[17];
    const float* mlp_w2 = (const float*)d_in[18];
    const float* mlp_b2 = (const float*)d_in[19];
    const float* fc_w1  = (const float*)d_in[20];
    const float* fc_b1  = (const float*)d_in[21];
    const float* fc_w2  = (const float*)d_in[22];
    const float* fc_b2  = (const float*)d_in[23];
    float* out = (float*)d_out;

    cudaFuncSetAttribute(k_conv, cudaFuncAttributeMaxDynamicSharedMemorySize, 87040);
    cudaFuncSetAttribute(k_attn, cudaFuncAttributeMaxDynamicSharedMemorySize, 104448);
    cudaFuncSetAttribute(k_mlp,  cudaFuncAttributeMaxDynamicSharedMemorySize, 92160);
    cudaFuncSetAttribute(k_dct,  cudaFuncAttributeMaxDynamicSharedMemorySize, 131072);
    cudaFuncSetAttribute(k_topk, cudaFuncAttributeMaxDynamicSharedMemorySize, 81920);

    // slot 4 (ncu capture) = k_conv
    k_ilv<<<NTOT / 4 / 256, 256>>>(x1, x2);
    k_weffP<<<36, 256>>>(w_tx1, lm1, theta1, w_tx2, lm2, theta2);
    k_prep2<<<241, 256>>>(qkv_w, qkv_b, proj_w, proj_b, mlp_w1, mlp_w2);
    k_conv<<<dim3(16, 12, 4), 256, 87040>>>();
    k_attn<<<1024, 256, 104448>>>(ln1_g, ln1_b);
    k_mlp<<<1024, 256, 92160>>>(ln2_g, ln2_b, mlp_b1, mlp_b2);
    k_init_dct<<<64, 256>>>();
    k_t2<<<dim3(512, 3, 4), dim3(32, 8)>>>();
    k_dct<<<384, 256, 131072>>>();
    k_energy<<<64, 256>>>();
    k_topk<<<4, 256, 81920>>>(fc_w1, fc_b1, fc_w2, fc_b2);
    k_final<<<NTOT / 4 / 256, 256>>>(x1, x2, out);
}

// round 8
// speedup vs baseline: 1.0958x; 1.0047x over previous
#include <cuda_runtime.h>
#include <math.h>

#define Bq   4
#define Cc   96
#define HWp  16384
#define NTOT (Bq*Cc*HWp)          // 6291456
#define CR3  36                    // new conv smem row stride (ull)
#define CTILE (66*CR3)             // 2376 ull per channel tile

typedef unsigned long long ull;

__device__ __forceinline__ ull pk2(float lo, float hi) {
    ull r; asm("mov.b64 %0,{%1,%2};" : "=l"(r) : "f"(lo), "f"(hi)); return r;
}
__device__ __forceinline__ void upk(ull v, float& lo, float& hi) {
    asm("mov.b64 {%0,%1},%2;" : "=f"(lo), "=f"(hi) : "l"(v));
}
__device__ __forceinline__ void ffma2(ull& d, ull a, ull b) {
    asm("fma.rn.f32x2 %0,%1,%2,%0;" : "+l"(d) : "l"(a), "l"(b));
}
__device__ __forceinline__ float gelu_ex(float x) {
    return 0.5f * x * (1.f + erff(x * 0.70710678118654752f));
}
__device__ __forceinline__ unsigned smem_u32(const void* p) {
    return (unsigned)__cvta_generic_to_shared(p);
}
__device__ __forceinline__ void cp16(unsigned dst, const void* src, int n) {
    asm volatile("cp.async.cg.shared.global [%0],[%1],16,%2;" :: "r"(dst), "l"(src), "r"(n));
}
#define CP_COMMIT() asm volatile("cp.async.commit_group;")
#define CP_WAIT0()  asm volatile("cp.async.wait_group 0;")

// ---------------- device scratch ----------------
__device__ ull   g_xi[NTOT];        // interleaved (x1,x2) pairs, CHW
__device__ ull   g_weffP[96*96*9];  // (w1eff,w2eff) pairs
__device__ float g_DT[128*128];
__device__ ull   g_DpD[128*128];    // dup pairs for DCT stage-1
__device__ ull   g_WcombP[96*96];   // dup
__device__ float g_bcomb[96];
__device__ ull   g_W1P[96*384];     // dup, [k*384+j]
__device__ ull   g_W2P[384*96];     // dup, [j*96+i]
__device__ float g_tokA[NTOT];
__device__ float g_tokB[NTOT];
__device__ float g_cross[NTOT];
__device__ float g_dct[NTOT];
__device__ float g_energy[Bq*HWp];
__device__ float g_scale[Bq];

// ---------------- interleave x1,x2 into pair array ----------------
__global__ void k_ilv(const float* __restrict__ x1, const float* __restrict__ x2) {
    int g = blockIdx.x * blockDim.x + threadIdx.x;   // NTOT/4
    float4 a = ((const float4*)x1)[g];
    float4 b = ((const float4*)x2)[g];
    ((float4*)g_xi)[2 * g]     = make_float4(a.x, b.x, a.y, b.y);
    ((float4*)g_xi)[2 * g + 1] = make_float4(a.z, b.z, a.w, b.w);
}

// ---------------- LDC effective weights, packed (w1,w2) ----------------
__global__ void k_weffP(const float* __restrict__ w1, const float* __restrict__ lm1,
                        const float* __restrict__ th1,
                        const float* __restrict__ w2, const float* __restrict__ lm2,
                        const float* __restrict__ th2) {
    int t = blockIdx.x * 256 + threadIdx.x;
    if (t >= 96 * 96) return;
    const float* ws1 = w1 + t * 9;
    const float* ws2 = w2 + t * 9;
    float s1 = 0.f, s2 = 0.f;
#pragma unroll
    for (int k = 0; k < 9; k++) { s1 += ws1[k]; s2 += ws2[k]; }
    float sc1 = 1.f - th1[0] * lm1[t] * s1;
    float sc2 = 1.f - th2[0] * lm2[t] * s2;
    ull* o = g_weffP + t * 9;
#pragma unroll
    for (int k = 0; k < 9; k++) o[k] = pk2(ws1[k], ws2[k]);
    o[4] = pk2(ws1[4] * sc1, ws2[4] * sc2);
}

// ---------------- init: DCT-II matrices ----------------
__global__ void k_init_dct() {
    int t = blockIdx.x * blockDim.x + threadIdx.x;   // 16384
    int k = t >> 7, i = t & 127;
    float arg = (float)((2 * i + 1) * k) * (1.0f / 256.0f);
    float v = cospif(arg) * 0.125f;
    if (k == 0) v *= 0.70710678118654752440f;
    g_DT[i * 128 + k] = v;
    g_DpD[((k >> 1) * 128 + i) * 2 + (k & 1)] = pk2(v, v);
}

// ---------------- prep: Wcomb dup, bcomb, MLP dup transposes ----------------
__global__ void k_prep2(const float* __restrict__ qkv_w, const float* __restrict__ qkv_b,
                        const float* __restrict__ proj_w, const float* __restrict__ proj_b,
                        const float* __restrict__ w1, const float* __restrict__ w2) {
    int blk = blockIdx.x, tid = threadIdx.x;
    if (blk < 96) {
        if (tid < 96) {
            float s = 0.f;
            for (int m = 0; m < 96; m++)
                s += proj_w[blk * 96 + m] * qkv_w[(192 + m) * 96 + tid];
            g_WcombP[tid * 96 + blk] = pk2(s, s);
        }
    } else if (blk == 96) {
        if (tid < 96) {
            float s = proj_b[tid];
            for (int m = 0; m < 96; m++)
                s += proj_w[tid * 96 + m] * qkv_b[192 + m];
            g_bcomb[tid] = s;
        }
    } else {
        int t = (blk - 97) * 256 + tid;
        if (t < 96 * 384) {
            { int k = t / 384, j = t % 384; float v = w1[j * 96 + k]; g_W1P[t] = pk2(v, v); }
            { int k = t / 96,  i = t % 96;  float v = w2[i * 384 + k]; g_W2P[t] = pk2(v, v); }
        }
    }
}

// ---------------- fused double conv + residual ----------------
// 8 pixels (4r x 2c) and 4 output channels per thread; tile 64x32 px.
// dynamic smem: sIn[2 buf][2 ch][66*36 ull] = 76032 B
__global__ void __launch_bounds__(256, 2)
k_conv() {
    extern __shared__ __align__(16) ull sIn[];
    __shared__ __align__(16) ull wS[2][2][4][10];     // [buf][ch][co][tap]
    __shared__ int2 slotS[5][256];                    // {goff or -1/-2, smem ull off}
    int tid = threadIdx.x;
    int b   = blockIdx.z;
    int cob = blockIdx.y * 4;                         // 24 co-blocks
    int bt  = blockIdx.x;                             // 8 tiles: 2 row x 4 col
    int y0  = (bt >> 2) * 64, x0 = (bt & 3) * 32;
    const ull* Xb = g_xi + (size_t)b * 96 * HWp;
    int ty = tid >> 4, tx = tid & 15;
    int rbase = ty * 4;
    int cbase = tx * 2 + 1;
    unsigned sbase = smem_u32(sIn);

    // channel-invariant load slots: 66 rows x 18 chunks (16B = 2 ull)
#pragma unroll
    for (int n = 0; n < 5; n++) {
        int s = tid + n * 256;
        if (s < 1188) {
            int r = s / 18, ch2 = s % 18;
            int gy = y0 - 1 + r;
            int gx = x0 - 2 + 2 * ch2;
            bool ok = (gy >= 0) && (gy < 128) && (gx >= 0) && (gx < 128);
            slotS[n][tid] = make_int2(ok ? (gy * 128 + gx) : -1, r * CR3 + 2 * ch2);
        } else {
            slotS[n][tid] = make_int2(-2, 0);
        }
    }
    __syncthreads();

    auto issue = [&](int st, int buf) {
#pragma unroll
        for (int c2 = 0; c2 < 2; c2++) {
            size_t gofs = (size_t)(2 * st + c2) * (HWp * 8);
            unsigned so = sbase + (unsigned)((buf * 2 + c2) * (CTILE * 8));
#pragma unroll
            for (int n = 0; n < 5; n++) {
                int2 sl = slotS[n][tid];
                if (sl.x != -2) {
                    int goff = sl.x < 0 ? 0 : sl.x;
                    cp16(so + (unsigned)sl.y * 8, (const char*)(Xb + goff) + gofs,
                         sl.x < 0 ? 0 : 16);
                }
            }
        }
        CP_COMMIT();
    };
    auto wload = [&](int st, int buf) {
        if (tid < 72) {
            int c2 = tid / 36, rr = tid % 36, co = rr / 9, k = rr % 9;
            wS[buf][c2][co][k] = g_weffP[((cob + co) * 96 + (2 * st + c2)) * 9 + k];
        }
    };

    issue(0, 0);
    wload(0, 0);

    ull acc[4][8];
#pragma unroll
    for (int i = 0; i < 4; i++)
#pragma unroll
        for (int j = 0; j < 8; j++) acc[i][j] = 0ULL;
    const ull TWO = pk2(2.f, 2.f);

    for (int st = 0; st < 48; st++) {
        int cur = st & 1;
        CP_WAIT0();
        __syncthreads();
        if (st < 47) { issue(st + 1, cur ^ 1); wload(st + 1, cur ^ 1); }

#pragma unroll
        for (int c2 = 0; c2 < 2; c2++) {
            const ull* tile = sIn + (cur * 2 + c2) * CTILE;
            ull rp[6][4];
#pragma unroll
            for (int i = 0; i < 6; i++)
#pragma unroll
                for (int j = 0; j < 4; j++)
                    rp[i][j] = tile[(rbase + i) * CR3 + cbase + j];

#pragma unroll
            for (int co = 0; co < 4; co++) {
#pragma unroll
                for (int ky = 0; ky < 3; ky++)
#pragma unroll
                    for (int kx = 0; kx < 3; kx++) {
                        ull w = wS[cur][c2][co][ky * 3 + kx];
#pragma unroll
                        for (int pr = 0; pr < 4; pr++) {
                            ffma2(acc[co][pr * 2 + 0], rp[pr + ky][kx],     w);
                            ffma2(acc[co][pr * 2 + 1], rp[pr + ky][kx + 1], w);
                        }
                    }
            }
            int cc = 2 * st + c2 - cob;
            if (cc >= 0 && cc < 4) {
#pragma unroll
                for (int pr = 0; pr < 4; pr++) {
                    ffma2(acc[cc][pr * 2 + 0], rp[pr + 1][1], TWO);
                    ffma2(acc[cc][pr * 2 + 1], rp[pr + 1][2], TWO);
                }
            }
        }
    }

    // store token-major: result = lo + hi (conv1(x1)+conv2(x2)+2(x1+x2))
#pragma unroll
    for (int pr = 0; pr < 4; pr++)
#pragma unroll
        for (int pc = 0; pc < 2; pc++) {
            float v[4];
#pragma unroll
            for (int co = 0; co < 4; co++) {
                float lo, hi; upk(acc[co][pr * 2 + pc], lo, hi);
                v[co] = lo + hi;
            }
            size_t tok = (size_t)b * HWp + (size_t)(y0 + ty * 4 + pr) * 128
                       + (x0 + tx * 2 + pc);
            *(float4*)(g_tokA + tok * 96 + cob) = make_float4(v[0], v[1], v[2], v[3]);
        }
}

// ---------------- swin attention (folded), smem-staged weights ----------------
__global__ void __launch_bounds__(256)
k_attn(const float* __restrict__ g1, const float* __restrict__ b1) {
    extern __shared__ __align__(16) ull dynsm[];
    ull*   wsm = dynsm;                       // 9216 ull
    float* tns = (float*)(dynsm + 9216);      // [8][960]
    int tid = threadIdx.x;
    int warp = tid >> 5, lane = tid & 31;
    int tokbase = blockIdx.x * 64 + warp * 8;
    float* tnw = tns + warp * 960;

#pragma unroll
    for (int i = 0; i < 18; i++) {
        int idx = tid + i * 256;
        cp16(smem_u32(wsm + 2 * idx), g_WcombP + 2 * idx, 16);
    }
    CP_COMMIT();

    float tv[8][3];
#pragma unroll
    for (int t = 0; t < 8; t++) {
        const float* tp = g_tokA + (size_t)(tokbase + t) * 96;
        float a = tp[lane], bb = tp[lane + 32], cc = tp[lane + 64];
        tv[t][0] = a; tv[t][1] = bb; tv[t][2] = cc;
        float s = a + bb + cc;
#pragma unroll
        for (int o = 16; o; o >>= 1) s += __shfl_xor_sync(0xffffffff, s, o);
        float m = s * (1.f / 96.f);
        float d0 = a - m, d1 = bb - m, d2 = cc - m;
        float q = d0 * d0 + d1 * d1 + d2 * d2;
#pragma unroll
        for (int o = 16; o; o >>= 1) q += __shfl_xor_sync(0xffffffff, q, o);
        float rstd = rsqrtf(q * (1.f / 96.f) + 1e-5f);
        tnw[lane * 10 + t]        = d0 * rstd * g1[lane]      + b1[lane];
        tnw[(lane + 32) * 10 + t] = d1 * rstd * g1[lane + 32] + b1[lane + 32];
        tnw[(lane + 64) * 10 + t] = d2 * rstd * g1[lane + 64] + b1[lane + 64];
    }
    CP_WAIT0();
    __syncthreads();

    ull acc[4][3];
#pragma unroll
    for (int p = 0; p < 4; p++) { acc[p][0] = 0; acc[p][1] = 0; acc[p][2] = 0; }
#pragma unroll 4
    for (int k = 0; k < 96; k++) {
        ull W0 = wsm[k * 96 + lane];
        ull W1 = wsm[k * 96 + lane + 32];
        ull W2 = wsm[k * 96 + lane + 64];
#pragma unroll
        for (int p = 0; p < 4; p++) {
            ull sp = *(const ull*)&tnw[k * 10 + 2 * p];
            ffma2(acc[p][0], sp, W0);
            ffma2(acc[p][1], sp, W1);
            ffma2(acc[p][2], sp, W2);
        }
    }
#pragma unroll
    for (int p = 0; p < 4; p++) {
#pragma unroll
        for (int c = 0; c < 3; c++) {
            float o0, o1; upk(acc[p][c], o0, o1);
            int ch = lane + 32 * c;
            g_tokB[(size_t)(tokbase + 2 * p) * 96 + ch]     = tv[2 * p][c]     + o0 + g_bcomb[ch];
            g_tokB[(size_t)(tokbase + 2 * p + 1) * 96 + ch] = tv[2 * p + 1][c] + o1 + g_bcomb[ch];
        }
    }
}

// ---------------- swin MLP, [ch][tok] smem, dup weights, j-halved ----------------
__global__ void __launch_bounds__(256)
k_mlp(const float* __restrict__ g2, const float* __restrict__ b2,
      const float* __restrict__ mb1, const float* __restrict__ mb2) {
    extern __shared__ float sm[];
    float* tnP = sm;            // [8][960]
    float* hsP = sm + 7680;     // [8][1920]
    int warp = threadIdx.x >> 5, lane = threadIdx.x & 31;
    int tokbase = blockIdx.x * 64 + warp * 8;
    float* tnw = tnP + warp * 960;
    float* hsw = hsP + warp * 1920;
    float tv[8][3];
#pragma unroll
    for (int t = 0; t < 8; t++) {
        const float* tp = g_tokB + (size_t)(tokbase + t) * 96;
        float a = tp[lane], bb = tp[lane + 32], cc = tp[lane + 64];
        tv[t][0] = a; tv[t][1] = bb; tv[t][2] = cc;
        float s = a + bb + cc;
#pragma unroll
        for (int o = 16; o; o >>= 1) s += __shfl_xor_sync(0xffffffff, s, o);
        float m = s * (1.f / 96.f);
        float d0 = a - m, d1 = bb - m, d2 = cc - m;
        float q = d0 * d0 + d1 * d1 + d2 * d2;
#pragma unroll
        for (int o = 16; o; o >>= 1) q += __shfl_xor_sync(0xffffffff, q, o);
        float rstd = rsqrtf(q * (1.f / 96.f) + 1e-5f);
        tnw[lane * 10 + t]        = d0 * rstd * g2[lane]      + b2[lane];
        tnw[(lane + 32) * 10 + t] = d1 * rstd * g2[lane + 32] + b2[lane + 32];
        tnw[(lane + 64) * 10 + t] = d2 * rstd * g2[lane + 64] + b2[lane + 64];
    }
    __syncwarp();
    ull oacc[4][3];
#pragma unroll
    for (int p = 0; p < 4; p++) { oacc[p][0] = 0; oacc[p][1] = 0; oacc[p][2] = 0; }

    for (int half = 0; half < 2; half++) {
        ull h[4][6];
#pragma unroll
        for (int p = 0; p < 4; p++)
#pragma unroll
            for (int r = 0; r < 6; r++) h[p][r] = 0;
        const ull* w1p = g_W1P + half * 192 + lane;
#pragma unroll 4
        for (int k = 0; k < 96; k++) {
            ull W[6];
#pragma unroll
            for (int r = 0; r < 6; r++) W[r] = w1p[k * 384 + 32 * r];
#pragma unroll
            for (int p = 0; p < 4; p++) {
                ull sp = *(const ull*)&tnw[k * 10 + 2 * p];
#pragma unroll
                for (int r = 0; r < 6; r++) ffma2(h[p][r], sp, W[r]);
            }
        }
#pragma unroll
        for (int p = 0; p < 4; p++)
#pragma unroll
            for (int r = 0; r < 6; r++) {
                int j = lane + 32 * r;
                float bias = mb1[half * 192 + j];
                float x0, x1; upk(h[p][r], x0, x1);
                hsw[j * 10 + 2 * p]     = gelu_ex(x0 + bias);
                hsw[j * 10 + 2 * p + 1] = gelu_ex(x1 + bias);
            }
        __syncwarp();
        const ull* w2p = g_W2P + (size_t)(half * 192) * 96;
#pragma unroll 4
        for (int j = 0; j < 192; j++) {
            ull U0 = w2p[j * 96 + lane];
            ull U1 = w2p[j * 96 + lane + 32];
            ull U2 = w2p[j * 96 + lane + 64];
#pragma unroll
            for (int p = 0; p < 4; p++) {
                ull hp = *(const ull*)&hsw[j * 10 + 2 * p];
                ffma2(oacc[p][0], hp, U0);
                ffma2(oacc[p][1], hp, U1);
                ffma2(oacc[p][2], hp, U2);
            }
        }
        __syncwarp();
    }
#pragma unroll
    for (int p = 0; p < 4; p++) {
#pragma unroll
        for (int c = 0; c < 3; c++) {
            float o0, o1; upk(oacc[p][c], o0, o1);
            int ch = lane + 32 * c;
            g_tokA[(size_t)(tokbase + 2 * p) * 96 + ch]     = tv[2 * p][c]     + o0 + mb2[ch];
            g_tokA[(size_t)(tokbase + 2 * p + 1) * 96 + ch] = tv[2 * p + 1][c] + o1 + mb2[ch];
        }
    }
}

// ---------------- transpose token-major -> CHW ----------------
__global__ void k_t2() {
    __shared__ float tile[32][33];
    int b = blockIdx.z, c0 = blockIdx.y * 32, p0 = blockIdx.x * 32;
    int tx = threadIdx.x, ty0 = threadIdx.y;
    for (int yy = ty0; yy < 32; yy += 8)
        tile[yy][tx] = g_tokA[(size_t)(b * HWp + p0 + yy) * 96 + c0 + tx];
    __syncthreads();
    for (int yy = ty0; yy < 32; yy += 8)
        g_cross[(size_t)(b * 96 + c0 + yy) * HWp + p0 + tx] = tile[tx][yy];
}

// ---------------- 2D DCT per (b,c) ----------------
__global__ void __launch_bounds__(256) k_dct() {
    extern __shared__ float sm[];
    float* Xs = sm;             // 16384
    float* Ys = sm + 16384;     // 16384
    int bc = blockIdx.x;
    int tid = threadIdx.x;
    const float4* src = (const float4*)(g_cross + (size_t)bc * HWp);
    float4* Xs4 = (float4*)Xs;
    for (int l = tid; l < 4096; l += 256) Xs4[l] = src[l];
    __syncthreads();

    int jq = tid & 31;
    int ig = tid >> 5;
    int j0 = 2 * jq, j2 = 64 + 2 * jq;

    for (int ii = 0; ii < 8; ii++) {
        int ip = ig + ii * 8;
        ull a00 = 0, a01 = 0, a10 = 0, a11 = 0;
        const ull* dp = g_DpD + ip * 256;
#pragma unroll 4
        for (int k = 0; k < 128; k++) {
            ull D0 = dp[2 * k], D1 = dp[2 * k + 1];
            ull xA = *(const ull*)&Xs[k * 128 + j0];
            ull xB = *(const ull*)&Xs[k * 128 + j2];
            ffma2(a00, xA, D0); ffma2(a01, xB, D0);
            ffma2(a10, xA, D1); ffma2(a11, xB, D1);
        }
        *(ull*)&Ys[(2 * ip) * 128 + j0]     = a00;
        *(ull*)&Ys[(2 * ip) * 128 + j2]     = a01;
        *(ull*)&Ys[(2 * ip + 1) * 128 + j0] = a10;
        *(ull*)&Ys[(2 * ip + 1) * 128 + j2] = a11;
    }
    __syncthreads();

    ull acc[8][4];
#pragma unroll
    for (int ii = 0; ii < 8; ii++)
#pragma unroll
        for (int q = 0; q < 4; q++) acc[ii][q] = 0;
#pragma unroll 2
    for (int k = 0; k < 128; k++) {
        ull dtA = *(const ull*)&g_DT[k * 128 + j0];
        ull dtB = *(const ull*)&g_DT[k * 128 + j2];
#pragma unroll
        for (int ii = 0; ii < 8; ii++) {
            int ip = ig + ii * 8;
            float y0 = Ys[(2 * ip) * 128 + k];
            float y1 = Ys[(2 * ip + 1) * 128 + k];
            ull Y0 = pk2(y0, y0), Y1 = pk2(y1, y1);
            ffma2(acc[ii][0], dtA, Y0); ffma2(acc[ii][1], dtB, Y0);
            ffma2(acc[ii][2], dtA, Y1); ffma2(acc[ii][3], dtB, Y1);
        }
    }
    float* dst = g_dct + (size_t)bc * HWp;
#pragma unroll
    for (int ii = 0; ii < 8; ii++) {
        int ip = ig + ii * 8;
        *(ull*)&dst[(2 * ip) * 128 + j0]     = acc[ii][0];
        *(ull*)&dst[(2 * ip) * 128 + j2]     = acc[ii][1];
        *(ull*)&dst[(2 * ip + 1) * 128 + j0] = acc[ii][2];
        *(ull*)&dst[(2 * ip + 1) * 128 + j2] = acc[ii][3];
    }
}

// ---------------- channel-mean |dct| (float4) ----------------
__global__ void k_energy() {
    int g = blockIdx.x * blockDim.x + threadIdx.x;   // 16384
    int b = g >> 12, p4 = g & 4095;
    const float4* base = (const float4*)(g_dct + (size_t)b * 96 * HWp) + p4;
    float4 s = make_float4(0.f, 0.f, 0.f, 0.f);
    for (int c = 0; c < 96; c++) {
        float4 v = base[(size_t)c * 4096];
        s.x += fabsf(v.x); s.y += fabsf(v.y); s.z += fabsf(v.z); s.w += fabsf(v.w);
    }
    float inv = 1.f / 96.f;
    s.x *= inv; s.y *= inv; s.z *= inv; s.w *= inv;
    ((float4*)(g_energy + b * HWp))[p4] = s;
}

// ---------------- top-96 via histogram threshold + rank sort ----------------
__global__ void __launch_bounds__(256)
k_topk(const float* __restrict__ fw1, const float* __restrict__ fb1,
       const float* __restrict__ fw2, const float* __restrict__ fb2) {
    extern __shared__ float e[];                 // 16384 floats
    int* hist = (int*)(e + 16384);               // 4096 ints (reused as cand)
    __shared__ int csum[256];
    __shared__ int s_T, s_cnt;
    __shared__ float tk[96];
    __shared__ float hh[24];
    int b = blockIdx.x, tid = threadIdx.x;

    const float4* src = (const float4*)(g_energy + b * HWp);
    float4* e4 = (float4*)e;
    for (int l = tid; l < 4096; l += 256) e4[l] = src[l];
    for (int l = tid; l < 4096; l += 256) hist[l] = 0;
    __syncthreads();
    for (int l = tid; l < 16384; l += 256) {
        int key = (int)(__float_as_uint(e[l]) >> 19);
        atomicAdd(&hist[key], 1);
    }
    __syncthreads();
    {
        int s = 0;
#pragma unroll
        for (int k = 0; k < 16; k++) s += hist[tid * 16 + k];
        csum[tid] = s;
    }
    __syncthreads();
    if (tid == 0) {
        int run = 0, cstar = 0;
        for (int c = 255; c >= 0; c--) {
            if (run + csum[c] >= 96) { cstar = c; break; }
            run += csum[c];
        }
        int T = cstar * 16;
        for (int k = 15; k >= 0; k--) {
            int bin = cstar * 16 + k;
            if (run + hist[bin] >= 96) { T = bin; break; }
            run += hist[bin];
        }
        s_T = T; s_cnt = 0;
    }
    __syncthreads();
    int T = s_T;
    float* cand = (float*)hist;
    __syncthreads();
    for (int l = tid; l < 16384; l += 256) {
        float v = e[l];
        if ((int)(__float_as_uint(v) >> 19) >= T) {
            int pos = atomicAdd(&s_cnt, 1);
            if (pos < 4096) cand[pos] = v;
        }
    }
    __syncthreads();
    int M = s_cnt; if (M > 4096) M = 4096;
    for (int i = tid; i < M; i += 256) {
        float v = cand[i];
        int r = 0;
        for (int j = 0; j < M; j++) {
            float u = cand[j];
            r += (u > v) || (u == v && j < i);
        }
        if (r < 96) tk[r] = v;
    }
    __syncthreads();
    if (tid < 24) {
        float s = fb1[tid];
        for (int k = 0; k < 96; k++) s += tk[k] * fw1[tid * 96 + k];
        hh[tid] = fmaxf(s, 0.f);
    }
    __syncthreads();
    if (tid == 0) {
        float a = fb2[0];
        for (int j = 0; j < 24; j++) a += hh[j] * fw2[j];
        g_scale[b] = 1.f + 1.f / (1.f + expf(-a));
    }
}

// ---------------- epilogue (float4) ----------------
__global__ void k_final(const float* __restrict__ x1, const float* __restrict__ x2,
                        float* __restrict__ out) {
    int i = blockIdx.x * blockDim.x + threadIdx.x;   // NTOT/4
    float s = g_scale[i / (96 * HWp / 4)];
    float4 c = ((const float4*)g_cross)[i];
    float4 a = ((const float4*)x1)[i];
    float4 b = ((const float4*)x2)[i];
    float4 o1, o2;
    o1.x = a.x + s * c.x; o1.y = a.y + s * c.y; o1.z = a.z + s * c.z; o1.w = a.w + s * c.w;
    o2.x = b.x + s * c.x; o2.y = b.y + s * c.y; o2.z = b.z + s * c.z; o2.w = b.w + s * c.w;
    ((float4*)out)[i]            = o1;
    ((float4*)out)[NTOT / 4 + i] = o2;
}

extern "C" void kernel_launch(void* const* d_in, const int* in_sizes, int n_in,
                              void* d_out, int out_size) {
    const float* x1     = (const float*)d_in[0];
    const float* x2     = (const float*)d_in[1];
    const float* w_tx1  = (const float*)d_in[2];
    const float* lm1    = (const float*)d_in[3];
    const float* theta1 = (const float*)d_in[4];
    const float* w_tx2  = (const float*)d_in[5];
    const float* lm2    = (const float*)d_in[6];
    const float* theta2 = (const float*)d_in[7];
    const float* ln1_g  = (const float*)d_in[8];
    const float* ln1_b  = (const float*)d_in[9];
    const float* qkv_w  = (const float*)d_in[10];
    const float* qkv_b  = (const float*)d_in[11];
    const float* proj_w = (const float*)d_in[12];
    const float* proj_b = (const float*)d_in[13];
    const float* ln2_g  = (const float*)d_in[14];
    const float* ln2_b  = (const float*)d_in[15];
    const float* mlp_w1 = (const float*)d_in[16];
    const float* mlp_b1 = (const float*)d_in[17];
    const float* mlp_w2 = (const float*)d_in[18];
    const float* mlp_b2 = (const float*)d_in[19];
    const float* fc_w1  = (const float*)d_in[20];
    const float* fc_b1  = (const float*)d_in[21];
    const float* fc_w2  = (const float*)d_in[22];
    const float* fc_b2  = (const float*)d_in[23];
    float* out = (float*)d_out;

    cudaFuncSetAttribute(k_conv, cudaFuncAttributeMaxDynamicSharedMemorySize, 76032);
    cudaFuncSetAttribute(k_attn, cudaFuncAttributeMaxDynamicSharedMemorySize, 104448);
    cudaFuncSetAttribute(k_mlp,  cudaFuncAttributeMaxDynamicSharedMemorySize, 92160);
    cudaFuncSetAttribute(k_dct,  cudaFuncAttributeMaxDynamicSharedMemorySize, 131072);
    cudaFuncSetAttribute(k_topk, cudaFuncAttributeMaxDynamicSharedMemorySize, 81920);

    // slot 4 (ncu capture) = k_conv
    k_ilv<<<NTOT / 4 / 256, 256>>>(x1, x2);
    k_weffP<<<36, 256>>>(w_tx1, lm1, theta1, w_tx2, lm2, theta2);
    k_prep2<<<241, 256>>>(qkv_w, qkv_b, proj_w, proj_b, mlp_w1, mlp_w2);
    k_conv<<<dim3(8, 24, 4), 256, 76032>>>();
    k_attn<<<1024, 256, 104448>>>(ln1_g, ln1_b);
    k_mlp<<<1024, 256, 92160>>>(ln2_g, ln2_b, mlp_b1, mlp_b2);
    k_init_dct<<<64, 256>>>();
    k_t2<<<dim3(512, 3, 4), dim3(32, 8)>>>();
    k_dct<<<384, 256, 131072>>>();
    k_energy<<<64, 256>>>();
    k_topk<<<4, 256, 81920>>>(fc_w1, fc_b1, fc_w2, fc_b2);
    k_final<<<NTOT / 4 / 256, 256>>>(x1, x2, out);
}